// round 1
// baseline (speedup 1.0000x reference)
#include <cuda_runtime.h>
#include <math.h>

#define B_    8
#define L_    160000
#define C_    4
#define NFFT_ 320
#define HOP_  160
#define LPAD_ (L_ + NFFT_)   // 160320
#define T_    1001
#define F_    161
#define KTAP  10

// ---------------- scratch (static device globals; no allocation) ----------------
__device__ float  g_xpad[B_*C_*LPAD_];          // padded, normalized signal
__device__ float2 g_X [(size_t)T_*B_*F_*C_];    // STFT  [t][b][k][c]
__device__ float2 g_Y [(size_t)2*B_*T_*F_];     // beams [beam][b][t][k]
__device__ float  g_fr[(size_t)2*B_*T_*NFFT_];  // istft frames [beam*B+b][t][n]
__device__ float4 g_psum[B_*32];
__device__ float  g_pmax[B_*32];
__device__ float  g_mean[B_*C_];
__device__ float  g_inv [B_];

__constant__ float c_c95[KTAP] = {0.95f, 0.0475f, 2.375e-3f, 1.1875e-4f, 5.9375e-6f,
                                  2.96875e-7f, 1.484375e-8f, 7.421875e-10f,
                                  3.7109375e-11f, 1.85546875e-12f};
__constant__ float c_p05[KTAP] = {1.0f, 0.05f, 2.5e-3f, 1.25e-4f, 6.25e-6f,
                                  3.125e-7f, 1.5625e-8f, 7.8125e-10f,
                                  3.90625e-11f, 1.953125e-12f};

// ---------------- complex helpers ----------------
__device__ __forceinline__ float2 cadd(float2 a, float2 b){ return make_float2(a.x+b.x, a.y+b.y); }
__device__ __forceinline__ float2 csub(float2 a, float2 b){ return make_float2(a.x-b.x, a.y-b.y); }
__device__ __forceinline__ float2 cmul(float2 a, float2 b){ return make_float2(a.x*b.x-a.y*b.y, a.x*b.y+a.y*b.x); }
// conj(a)*b
__device__ __forceinline__ float2 ccmul(float2 a, float2 b){ return make_float2(a.x*b.x+a.y*b.y, a.x*b.y-a.y*b.x); }
// a*conj(b)
__device__ __forceinline__ float2 cmulc(float2 a, float2 b){ return make_float2(a.x*b.x+a.y*b.y, a.y*b.x-a.x*b.y); }
__device__ __forceinline__ float2 cscale(float s, float2 a){ return make_float2(s*a.x, s*a.y); }

// ---------------- stats ----------------
__global__ void k_sum(const float* __restrict__ x){
    int b = blockIdx.y, ch = blockIdx.x;
    int l0 = ch*5000;
    float4 acc = make_float4(0.f,0.f,0.f,0.f);
    for(int l = l0 + threadIdx.x; l < l0+5000; l += 256){
        float4 v = *(const float4*)(x + ((size_t)b*L_ + l)*C_);
        acc.x += v.x; acc.y += v.y; acc.z += v.z; acc.w += v.w;
    }
    __shared__ float4 red[256];
    red[threadIdx.x] = acc; __syncthreads();
    for(int s = 128; s > 0; s >>= 1){
        if(threadIdx.x < s){
            float4 o = red[threadIdx.x+s];
            red[threadIdx.x].x += o.x; red[threadIdx.x].y += o.y;
            red[threadIdx.x].z += o.z; red[threadIdx.x].w += o.w;
        }
        __syncthreads();
    }
    if(threadIdx.x == 0) g_psum[b*32+ch] = red[0];
}

__global__ void k_mean(){
    int tid = threadIdx.x;
    if(tid >= B_*C_) return;
    int b = tid >> 2, c = tid & 3;
    float s = 0.f;
    for(int i = 0; i < 32; i++){
        float4 v = g_psum[b*32+i];
        s += (c==0)?v.x:(c==1)?v.y:(c==2)?v.z:v.w;
    }
    g_mean[tid] = s / (float)L_;
}

__global__ void k_max(const float* __restrict__ x){
    int b = blockIdx.y, ch = blockIdx.x;
    float m0 = g_mean[b*4+0], m1 = g_mean[b*4+1], m2 = g_mean[b*4+2], m3 = g_mean[b*4+3];
    int l0 = ch*5000;
    float m = 0.f;
    for(int l = l0 + threadIdx.x; l < l0+5000; l += 256){
        float4 v = *(const float4*)(x + ((size_t)b*L_ + l)*C_);
        m = fmaxf(m, fabsf(v.x-m0)); m = fmaxf(m, fabsf(v.y-m1));
        m = fmaxf(m, fabsf(v.z-m2)); m = fmaxf(m, fabsf(v.w-m3));
    }
    __shared__ float red[256];
    red[threadIdx.x] = m; __syncthreads();
    for(int s = 128; s > 0; s >>= 1){
        if(threadIdx.x < s) red[threadIdx.x] = fmaxf(red[threadIdx.x], red[threadIdx.x+s]);
        __syncthreads();
    }
    if(threadIdx.x == 0) g_pmax[b*32+ch] = red[0];
}

__global__ void k_inv(){
    int b = threadIdx.x;
    if(b >= B_) return;
    float m = 0.f;
    for(int i = 0; i < 32; i++) m = fmaxf(m, g_pmax[b*32+i]);
    g_inv[b] = 1.0f/m;
}

// ---------------- pad + normalize (reflect) ----------------
__global__ void k_pad(const float* __restrict__ x){
    int idx = blockIdx.x*blockDim.x + threadIdx.x;
    if(idx >= B_*C_*LPAD_) return;
    int b = idx / (C_*LPAD_);
    int r = idx % (C_*LPAD_);
    int c = r / LPAD_;
    int p = r % LPAD_;
    int l = p - (NFFT_/2);
    if(l < 0) l = -l;
    else if(l >= L_) l = 2*L_ - 2 - l;
    float v = x[((size_t)b*L_ + l)*C_ + c];
    g_xpad[idx] = (v - g_mean[b*4+c]) * g_inv[b];
}

// ---------------- STFT: 320 = 16 x 20 Cooley-Tukey, block per (b,t), 4 channels ----------------
__global__ void k_stft(const float* __restrict__ win){
    int t = blockIdx.x, b = blockIdx.y;
    int tid = threadIdx.x;
    __shared__ float  sv[C_][NFFT_];
    __shared__ float2 sW320[NFFT_];     // e^{-2pi i j/320}
    __shared__ float2 sW16[16];         // e^{-2pi i j/16}
    __shared__ float2 sG[C_][9][20];    // inner DFT16 results, m=0..8

    for(int i = tid; i < C_*NFFT_; i += 256){
        int c = i / NFFT_, n = i % NFFT_;
        sv[c][n] = g_xpad[((size_t)(b*C_+c))*LPAD_ + (size_t)t*HOP_ + n] * win[n];
    }
    for(int j = tid; j < NFFT_; j += 256){
        float s, c; sincospif(-(float)j/160.0f, &s, &c);
        sW320[j] = make_float2(c, s);
    }
    if(tid < 16){
        float s, c; sincospif(-(float)tid/8.0f, &s, &c);
        sW16[tid] = make_float2(c, s);
    }
    __syncthreads();

    // stage 1: G[c][m][r] = sum_q v[20q+r] * W16^{qm}
    for(int task = tid; task < C_*20*9; task += 256){
        int c = task/180, rm = task%180, r = rm/9, m = rm%9;
        float re = 0.f, im = 0.f;
        #pragma unroll
        for(int q = 0; q < 16; q++){
            float2 w = sW16[(q*m) & 15];
            float v = sv[c][20*q + r];
            re += v*w.x; im += v*w.y;
        }
        sG[c][m][r] = make_float2(re, im);
    }
    __syncthreads();

    // stage 2: X[k] = sum_r W320^{kr} * G[r][k mod 16]
    for(int task = tid; task < C_*F_; task += 256){
        int c = task/F_, k = task%F_;
        int m = k & 15;
        bool hi = (m > 8);
        int mm = hi ? 16-m : m;
        float sgn = hi ? -1.f : 1.f;
        float2 acc = make_float2(0.f, 0.f);
        int idx = 0;
        #pragma unroll
        for(int r = 0; r < 20; r++){
            float2 g = sG[c][mm][r]; g.y *= sgn;
            float2 w = sW320[idx];
            acc.x += w.x*g.x - w.y*g.y;
            acc.y += w.x*g.y + w.y*g.x;
            idx += k; if(idx >= NFFT_) idx -= NFFT_;
        }
        g_X[(((size_t)t*B_ + b)*F_ + k)*C_ + c] = acc;
    }
}

// ---------------- MVDR per (t,b,k): truncated IIR covariance + LDL^H solve ----------------
struct LDLf { float iD0,iD1,iD2,iD3; float2 L10,L20,L30,L21,L31,L32; };

__device__ __forceinline__ float2 mvdr_beam(const LDLf& f,
    float2 h0, float2 h1, float2 h2, float2 h3,
    float2 X0, float2 X1, float2 X2, float2 X3)
{
    // forward: L z = h (unit lower)
    float2 z0 = h0;
    float2 z1 = csub(h1, cmul(f.L10, z0));
    float2 z2 = csub(csub(h2, cmul(f.L20, z0)), cmul(f.L21, z1));
    float2 z3 = csub(csub(csub(h3, cmul(f.L30, z0)), cmul(f.L31, z1)), cmul(f.L32, z2));
    float2 u0 = cscale(f.iD0, z0), u1 = cscale(f.iD1, z1);
    float2 u2 = cscale(f.iD2, z2), u3 = cscale(f.iD3, z3);
    // backward: L^H y = u
    float2 y3 = u3;
    float2 y2 = csub(u2, ccmul(f.L32, y3));
    float2 y1 = csub(csub(u1, ccmul(f.L21, y2)), ccmul(f.L31, y3));
    float2 y0 = csub(csub(csub(u0, ccmul(f.L10, y1)), ccmul(f.L20, y2)), ccmul(f.L30, y3));
    // den = h^H y ; s = y^H X ; out = s / conj(den)
    float2 den = cadd(cadd(ccmul(h0,y0), ccmul(h1,y1)), cadd(ccmul(h2,y2), ccmul(h3,y3)));
    float2 s   = cadd(cadd(ccmul(y0,X0), ccmul(y1,X1)), cadd(ccmul(y2,X2), ccmul(y3,X3)));
    float inv = 1.0f/(den.x*den.x + den.y*den.y);
    float2 sd = cmul(s, den);
    return make_float2(sd.x*inv, sd.y*inv);
}

__global__ void k_beam(){
    int t = blockIdx.x, b = blockIdx.y, k = threadIdx.x;
    if(k >= F_) return;

    const float4* pX = (const float4*)&g_X[(((size_t)t*B_ + b)*F_ + k)*C_];
    float4 xa = pX[0], xb = pX[1];
    float2 X0 = make_float2(xa.x,xa.y), X1 = make_float2(xa.z,xa.w);
    float2 X2 = make_float2(xb.x,xb.y), X3 = make_float2(xb.z,xb.w);

    float d0=0,d1=0,d2=0,d3=0;
    float2 m10={0,0}, m20={0,0}, m21={0,0}, m30={0,0}, m31={0,0}, m32={0,0};

    #pragma unroll
    for(int j = 0; j < KTAP; j++){
        int s = t - j;
        if(s < 0) break;
        float cf = (s == 0) ? c_p05[t] : c_c95[j];
        float2 y0,y1,y2,y3;
        if(j == 0){ y0=X0; y1=X1; y2=X2; y3=X3; }
        else{
            const float4* p = (const float4*)&g_X[(((size_t)s*B_ + b)*F_ + k)*C_];
            float4 a = p[0], bb = p[1];
            y0 = make_float2(a.x,a.y); y1 = make_float2(a.z,a.w);
            y2 = make_float2(bb.x,bb.y); y3 = make_float2(bb.z,bb.w);
        }
        float2 u0 = cscale(cf,y0), u1 = cscale(cf,y1), u2 = cscale(cf,y2), u3 = cscale(cf,y3);
        d0 += u0.x*y0.x + u0.y*y0.y;
        d1 += u1.x*y1.x + u1.y*y1.y;
        d2 += u2.x*y2.x + u2.y*y2.y;
        d3 += u3.x*y3.x + u3.y*y3.y;
        m10 = cadd(m10, cmulc(u1,y0));
        m20 = cadd(m20, cmulc(u2,y0));
        m21 = cadd(m21, cmulc(u2,y1));
        m30 = cadd(m30, cmulc(u3,y0));
        m31 = cadd(m31, cmulc(u3,y1));
        m32 = cadd(m32, cmulc(u3,y2));
    }

    // diagonal loading: A = R + (tr/4) I
    float tr4 = 0.25f*(d0+d1+d2+d3);
    float a0 = d0+tr4, a1 = d1+tr4, a2 = d2+tr4, a3 = d3+tr4;

    // LDL^H
    LDLf f;
    f.iD0 = 1.0f/a0;
    f.L10 = cscale(f.iD0, m10); f.L20 = cscale(f.iD0, m20); f.L30 = cscale(f.iD0, m30);
    float D1 = a1 - (m10.x*f.L10.x + m10.y*f.L10.y);
    f.iD1 = 1.0f/D1;
    float2 t21 = csub(m21, cmulc(m20, f.L10));
    f.L21 = cscale(f.iD1, t21);
    float2 t31 = csub(m31, cmulc(m30, f.L10));
    f.L31 = cscale(f.iD1, t31);
    float D2 = a2 - (m20.x*f.L20.x + m20.y*f.L20.y) - (t21.x*f.L21.x + t21.y*f.L21.y);
    f.iD2 = 1.0f/D2;
    float2 t32 = csub(csub(m32, cmulc(m30, f.L20)), cmulc(t31, f.L21));
    f.L32 = cscale(f.iD2, t32);
    float D3 = a3 - (m30.x*f.L30.x + m30.y*f.L30.y)
                  - (t31.x*f.L31.x + t31.y*f.L31.y)
                  - (t32.x*f.L32.x + t32.y*f.L32.y);
    f.iD3 = 1.0f/D3;

    // steering: phi = 2*pi*(50k)*0.027*sin(40deg)/340 ; h(+40)=e^{+i c phi}, h(-40)=conj
    const float phi = (float)(6.283185307179586 * 50.0 * 0.027 * 0.6427876096865393 / 340.0);
    float a = phi * (float)k;
    float s1, c1; sincosf(a, &s1, &c1);
    float c2 = c1*c1 - s1*s1, s2 = 2.f*c1*s1;
    float c3 = c2*c1 - s2*s1, s3 = s2*c1 + c2*s1;

    float2 one = make_float2(1.f, 0.f);
    // beam 0: angle -40 (conjugate phases)
    float2 o1 = mvdr_beam(f, one, make_float2(c1,-s1), make_float2(c2,-s2), make_float2(c3,-s3),
                          X0, X1, X2, X3);
    // beam 1: angle +40
    float2 o2 = mvdr_beam(f, one, make_float2(c1, s1), make_float2(c2, s2), make_float2(c3, s3),
                          X0, X1, X2, X3);

    g_Y[((size_t)(0*B_+b)*T_ + t)*F_ + k] = o1;
    g_Y[((size_t)(1*B_+b)*T_ + t)*F_ + k] = o2;
}

// ---------------- ISTFT frames: inverse 320-DFT via 16 x 20 factorization ----------------
__global__ void k_istft(){
    int t = blockIdx.x, b = blockIdx.y, beam = blockIdx.z;
    int tid = threadIdx.x;
    __shared__ float2 sY[F_];
    __shared__ float2 sH[16][20];
    __shared__ float2 sWp[NFFT_];  // e^{+2pi i j/320}
    __shared__ float2 sW20[20];    // e^{+2pi i j/20}

    size_t base = ((size_t)(beam*B_+b)*T_ + t)*F_;
    if(tid < F_) sY[tid] = g_Y[base + tid];
    {
        float s, c; sincospif((float)tid/160.0f, &s, &c);
        sWp[tid] = make_float2(c, s);
    }
    if(tid < 20){
        float s, c; sincospif((float)tid/10.0f, &s, &c);
        sW20[tid] = make_float2(c, s);
    }
    __syncthreads();

    // stage A: H[k1][p] = sum_{k2<20} Z[16 k2 + k1] * W20^{k2 p}
    {
        int k1 = tid & 15, p = tid >> 4;   // 320 threads exactly
        float2 acc = make_float2(0.f, 0.f);
        int idx = 0;
        #pragma unroll
        for(int k2 = 0; k2 < 20; k2++){
            int kk = 16*k2 + k1;
            float2 z;
            if(kk <= 160){
                z = sY[kk];
                if(kk == 0 || kk == 160) z.y = 0.f;  // c2r ignores imag of DC/Nyquist
            } else {
                z = sY[320-kk]; z.y = -z.y;
            }
            float2 w = sW20[idx];
            acc.x += z.x*w.x - z.y*w.y;
            acc.y += z.x*w.y + z.y*w.x;
            idx += p; if(idx >= 20) idx -= 20;
        }
        sH[k1][p] = acc;
    }
    __syncthreads();

    // stage B: x[n] = (1/320) Re( sum_{k1<16} Wp^{k1 n} H[k1][n mod 20] ), fold OLA 1/2
    {
        int n = tid;
        int pm = n % 20;
        float acc = 0.f;
        int idx = 0;
        #pragma unroll
        for(int k1 = 0; k1 < 16; k1++){
            float2 h = sH[k1][pm];
            float2 w = sWp[idx];
            acc += w.x*h.x - w.y*h.y;
            idx += n; if(idx >= NFFT_) idx -= NFFT_;
        }
        g_fr[((size_t)(beam*B_+b)*T_ + t)*NFFT_ + n] = acc * (1.0f/640.0f);
    }
}

// ---------------- overlap-add (exactly 2 frames per sample) ----------------
__global__ void k_ola(float* __restrict__ out){
    int idx = blockIdx.x*blockDim.x + threadIdx.x;
    if(idx >= 2*B_*L_) return;
    int bb = idx / L_;
    int l  = idx % L_;
    int q   = l/160 + 1;
    int rem = l - (q-1)*160;
    out[idx] = g_fr[((size_t)bb*T_ + q)*NFFT_ + rem]
             + g_fr[((size_t)bb*T_ + (q-1))*NFFT_ + rem + 160];
}

// ---------------- launch ----------------
extern "C" void kernel_launch(void* const* d_in, const int* in_sizes, int n_in,
                              void* d_out, int out_size){
    const float* x   = (const float*)d_in[0];
    const float* win = (const float*)d_in[1];
    float* out = (float*)d_out;

    k_sum <<<dim3(32, B_), 256>>>(x);
    k_mean<<<1, 32>>>();
    k_max <<<dim3(32, B_), 256>>>(x);
    k_inv <<<1, 8>>>();
    k_pad <<<(B_*C_*LPAD_ + 255)/256, 256>>>(x);
    k_stft<<<dim3(T_, B_), 256>>>(win);
    k_beam<<<dim3(T_, B_), 192>>>();
    k_istft<<<dim3(T_, B_, 2), NFFT_>>>();
    k_ola <<<(2*B_*L_ + 255)/256, 256>>>(out);
}

// round 3
// speedup vs baseline: 1.2924x; 1.2924x over previous
#include <cuda_runtime.h>
#include <math.h>

#define B_    8
#define L_    160000
#define C_    4
#define NFFT_ 320
#define HOP_  160
#define T_    1001
#define F_    161
#define KTAP  10
#define BT    128        // beam t-tile
#define IT    4          // istft frames per block

// ---------------- scratch ----------------
__device__ float2 g_X [(size_t)B_*F_*T_*C_];    // STFT  [b][k][t][c]
__device__ float2 g_Y [(size_t)2*B_*F_*T_];     // beams [beam][b][k][t]
__device__ float  g_fr[(size_t)2*B_*T_*NFFT_];  // istft frames [beam*B+b][t][n]
__device__ float4 g_ssum[B_*32];
__device__ float4 g_smax[B_*32];
__device__ float4 g_smin[B_*32];

__constant__ float c_c95[KTAP] = {0.95f, 0.0475f, 2.375e-3f, 1.1875e-4f, 5.9375e-6f,
                                  2.96875e-7f, 1.484375e-8f, 7.421875e-10f,
                                  3.7109375e-11f, 1.85546875e-12f};
__constant__ float c_p05[KTAP] = {1.0f, 0.05f, 2.5e-3f, 1.25e-4f, 6.25e-6f,
                                  3.125e-7f, 1.5625e-8f, 7.8125e-10f,
                                  3.90625e-11f, 1.953125e-12f};

// ---------------- complex helpers ----------------
__device__ __forceinline__ float2 cadd(float2 a, float2 b){ return make_float2(a.x+b.x, a.y+b.y); }
__device__ __forceinline__ float2 csub(float2 a, float2 b){ return make_float2(a.x-b.x, a.y-b.y); }
__device__ __forceinline__ float2 cmul(float2 a, float2 b){ return make_float2(a.x*b.x-a.y*b.y, a.x*b.y+a.y*b.x); }
__device__ __forceinline__ float2 ccmul(float2 a, float2 b){ return make_float2(a.x*b.x+a.y*b.y, a.x*b.y-a.y*b.x); } // conj(a)*b
__device__ __forceinline__ float2 cmulc(float2 a, float2 b){ return make_float2(a.x*b.x+a.y*b.y, a.y*b.x-a.x*b.y); } // a*conj(b)
__device__ __forceinline__ float2 cscale(float s, float2 a){ return make_float2(s*a.x, s*a.y); }

// ---------------- single-pass stats: sum / max / min per (b, chunk) ----------------
__global__ void k_stats(const float* __restrict__ x){
    int b = blockIdx.y, ch = blockIdx.x;
    int l0 = ch*5000;
    float4 s  = make_float4(0.f,0.f,0.f,0.f);
    float4 mx = make_float4(-1e30f,-1e30f,-1e30f,-1e30f);
    float4 mn = make_float4( 1e30f, 1e30f, 1e30f, 1e30f);
    for(int l = l0 + threadIdx.x; l < l0+5000; l += 256){
        float4 v = *(const float4*)(x + ((size_t)b*L_ + l)*C_);
        s.x += v.x; s.y += v.y; s.z += v.z; s.w += v.w;
        mx.x = fmaxf(mx.x,v.x); mx.y = fmaxf(mx.y,v.y); mx.z = fmaxf(mx.z,v.z); mx.w = fmaxf(mx.w,v.w);
        mn.x = fminf(mn.x,v.x); mn.y = fminf(mn.y,v.y); mn.z = fminf(mn.z,v.z); mn.w = fminf(mn.w,v.w);
    }
    __shared__ float4 rs[256], rx[256], rn[256];
    rs[threadIdx.x]=s; rx[threadIdx.x]=mx; rn[threadIdx.x]=mn; __syncthreads();
    for(int st = 128; st > 0; st >>= 1){
        if(threadIdx.x < st){
            float4 o = rs[threadIdx.x+st];
            rs[threadIdx.x].x += o.x; rs[threadIdx.x].y += o.y; rs[threadIdx.x].z += o.z; rs[threadIdx.x].w += o.w;
            float4 a = rx[threadIdx.x+st];
            rx[threadIdx.x].x = fmaxf(rx[threadIdx.x].x,a.x); rx[threadIdx.x].y = fmaxf(rx[threadIdx.x].y,a.y);
            rx[threadIdx.x].z = fmaxf(rx[threadIdx.x].z,a.z); rx[threadIdx.x].w = fmaxf(rx[threadIdx.x].w,a.w);
            float4 c = rn[threadIdx.x+st];
            rn[threadIdx.x].x = fminf(rn[threadIdx.x].x,c.x); rn[threadIdx.x].y = fminf(rn[threadIdx.x].y,c.y);
            rn[threadIdx.x].z = fminf(rn[threadIdx.x].z,c.z); rn[threadIdx.x].w = fminf(rn[threadIdx.x].w,c.w);
        }
        __syncthreads();
    }
    if(threadIdx.x == 0){
        g_ssum[b*32+ch] = rs[0]; g_smax[b*32+ch] = rx[0]; g_smin[b*32+ch] = rn[0];
    }
}

// ---------------- STFT: fused stats-finalize + reflect-pad + normalize + window + 16x20 DFT ----------------
__global__ void k_stft(const float* __restrict__ x, const float* __restrict__ win){
    int t = blockIdx.x, b = blockIdx.y;
    int tid = threadIdx.x;
    __shared__ float  sv[C_][NFFT_];
    __shared__ float2 sW320[NFFT_];
    __shared__ float2 sW16[16];
    __shared__ float2 sG[C_][9][20];
    __shared__ float  sMean[4];
    __shared__ float  sInv;

    // finalize stats (warp 0)
    if(tid < 32){
        float4 s  = g_ssum[b*32+tid];
        float4 mx = g_smax[b*32+tid];
        float4 mn = g_smin[b*32+tid];
        for(int o = 16; o; o >>= 1){
            s.x += __shfl_xor_sync(~0u, s.x, o); s.y += __shfl_xor_sync(~0u, s.y, o);
            s.z += __shfl_xor_sync(~0u, s.z, o); s.w += __shfl_xor_sync(~0u, s.w, o);
            mx.x = fmaxf(mx.x, __shfl_xor_sync(~0u, mx.x, o)); mx.y = fmaxf(mx.y, __shfl_xor_sync(~0u, mx.y, o));
            mx.z = fmaxf(mx.z, __shfl_xor_sync(~0u, mx.z, o)); mx.w = fmaxf(mx.w, __shfl_xor_sync(~0u, mx.w, o));
            mn.x = fminf(mn.x, __shfl_xor_sync(~0u, mn.x, o)); mn.y = fminf(mn.y, __shfl_xor_sync(~0u, mn.y, o));
            mn.z = fminf(mn.z, __shfl_xor_sync(~0u, mn.z, o)); mn.w = fminf(mn.w, __shfl_xor_sync(~0u, mn.w, o));
        }
        if(tid == 0){
            float m0 = s.x/(float)L_, m1 = s.y/(float)L_, m2 = s.z/(float)L_, m3 = s.w/(float)L_;
            float a = fmaxf(fmaxf(mx.x-m0, m0-mn.x), fmaxf(mx.y-m1, m1-mn.y));
            a = fmaxf(a, fmaxf(fmaxf(mx.z-m2, m2-mn.z), fmaxf(mx.w-m3, m3-mn.w)));
            sMean[0]=m0; sMean[1]=m1; sMean[2]=m2; sMean[3]=m3; sInv = 1.0f/a;
        }
    }
    for(int j = tid; j < NFFT_; j += 256){
        float sn, cs; sincospif(-(float)j/160.0f, &sn, &cs);
        sW320[j] = make_float2(cs, sn);
    }
    if(tid < 16){
        float sn, cs; sincospif(-(float)tid/8.0f, &sn, &cs);
        sW16[tid] = make_float2(cs, sn);
    }
    __syncthreads();

    float m0 = sMean[0], m1 = sMean[1], m2 = sMean[2], m3 = sMean[3], inv = sInv;
    for(int n = tid; n < NFFT_; n += 256){
        int l = t*HOP_ + n - (NFFT_/2);
        if(l < 0) l = -l;
        else if(l >= L_) l = 2*L_ - 2 - l;
        float4 v = *(const float4*)(x + ((size_t)b*L_ + l)*C_);
        float w = win[n] * inv;
        sv[0][n] = (v.x-m0)*w; sv[1][n] = (v.y-m1)*w; sv[2][n] = (v.z-m2)*w; sv[3][n] = (v.w-m3)*w;
    }
    __syncthreads();

    // stage 1: G[c][m][r] = sum_q v[20q+r] * W16^{qm}
    for(int task = tid; task < C_*20*9; task += 256){
        int c = task/180, rm = task%180, r = rm/9, m = rm%9;
        float re = 0.f, im = 0.f;
        #pragma unroll
        for(int q = 0; q < 16; q++){
            float2 w = sW16[(q*m) & 15];
            float v = sv[c][20*q + r];
            re += v*w.x; im += v*w.y;
        }
        sG[c][m][r] = make_float2(re, im);
    }
    __syncthreads();

    // stage 2: X[k] = sum_r W320^{kr} * G[r][k mod 16]; groups of 4 threads share k (coalesced 32B writes)
    for(int task = tid; task < F_*C_; task += 256){
        int k = task >> 2, c = task & 3;
        int m = k & 15;
        bool hi = (m > 8);
        int mm = hi ? 16-m : m;
        float sgn = hi ? -1.f : 1.f;
        float2 acc = make_float2(0.f, 0.f);
        int idx = 0;
        #pragma unroll
        for(int r = 0; r < 20; r++){
            float2 g = sG[c][mm][r]; g.y *= sgn;
            float2 w = sW320[idx];
            acc.x += w.x*g.x - w.y*g.y;
            acc.y += w.x*g.y + w.y*g.x;
            idx += k; if(idx >= NFFT_) idx -= NFFT_;
        }
        g_X[(((size_t)b*F_ + k)*T_ + t)*C_ + c] = acc;
    }
}

// ---------------- MVDR beam: t-tiled in shared, LDL^H solve ----------------
struct LDLf { float iD0,iD1,iD2,iD3; float2 L10,L20,L30,L21,L31,L32; };

__device__ __forceinline__ float2 mvdr_beam(const LDLf& f,
    float2 h0, float2 h1, float2 h2, float2 h3,
    float2 X0, float2 X1, float2 X2, float2 X3)
{
    float2 z0 = h0;
    float2 z1 = csub(h1, cmul(f.L10, z0));
    float2 z2 = csub(csub(h2, cmul(f.L20, z0)), cmul(f.L21, z1));
    float2 z3 = csub(csub(csub(h3, cmul(f.L30, z0)), cmul(f.L31, z1)), cmul(f.L32, z2));
    float2 u0 = cscale(f.iD0, z0), u1 = cscale(f.iD1, z1);
    float2 u2 = cscale(f.iD2, z2), u3 = cscale(f.iD3, z3);
    float2 y3 = u3;
    float2 y2 = csub(u2, ccmul(f.L32, y3));
    float2 y1 = csub(csub(u1, ccmul(f.L21, y2)), ccmul(f.L31, y3));
    float2 y0 = csub(csub(csub(u0, ccmul(f.L10, y1)), ccmul(f.L20, y2)), ccmul(f.L30, y3));
    float2 den = cadd(cadd(ccmul(h0,y0), ccmul(h1,y1)), cadd(ccmul(h2,y2), ccmul(h3,y3)));
    float2 s   = cadd(cadd(ccmul(y0,X0), ccmul(y1,X1)), cadd(ccmul(y2,X2), ccmul(y3,X3)));
    float inv = 1.0f/(den.x*den.x + den.y*den.y);
    float2 sd = cmul(s, den);
    return make_float2(sd.x*inv, sd.y*inv);
}

__global__ void k_beam(){
    int tb = blockIdx.x, b = blockIdx.y, k = blockIdx.z;
    int tid = threadIdx.x;
    __shared__ float4 sX[(BT + KTAP - 1)*2];

    int ts = tb*BT - (KTAP-1);
    const float4* gx = (const float4*)g_X + ((size_t)(b*F_ + k))*T_*2;
    for(int i = tid; i < (BT + KTAP - 1)*2; i += BT){
        int tt = ts + (i >> 1);
        if(tt >= 0 && tt < T_) sX[i] = gx[(size_t)tt*2 + (i & 1)];
    }
    __syncthreads();

    int t = tb*BT + tid;
    if(t >= T_) return;

    int base = (tid + KTAP - 1)*2;
    float4 xa = sX[base], xb = sX[base+1];
    float2 X0 = make_float2(xa.x,xa.y), X1 = make_float2(xa.z,xa.w);
    float2 X2 = make_float2(xb.x,xb.y), X3 = make_float2(xb.z,xb.w);

    float d0=0,d1=0,d2=0,d3=0;
    float2 m10={0,0}, m20={0,0}, m21={0,0}, m30={0,0}, m31={0,0}, m32={0,0};

    #pragma unroll
    for(int j = 0; j < KTAP; j++){
        int s = t - j;
        if(s < 0) break;
        float cf = (s == 0) ? c_p05[t] : c_c95[j];
        float2 y0,y1,y2,y3;
        if(j == 0){ y0=X0; y1=X1; y2=X2; y3=X3; }
        else{
            float4 a = sX[base - 2*j], bb = sX[base - 2*j + 1];
            y0 = make_float2(a.x,a.y); y1 = make_float2(a.z,a.w);
            y2 = make_float2(bb.x,bb.y); y3 = make_float2(bb.z,bb.w);
        }
        float2 u0 = cscale(cf,y0), u1 = cscale(cf,y1), u2 = cscale(cf,y2), u3 = cscale(cf,y3);
        d0 += u0.x*y0.x + u0.y*y0.y;
        d1 += u1.x*y1.x + u1.y*y1.y;
        d2 += u2.x*y2.x + u2.y*y2.y;
        d3 += u3.x*y3.x + u3.y*y3.y;
        m10 = cadd(m10, cmulc(u1,y0));
        m20 = cadd(m20, cmulc(u2,y0));
        m21 = cadd(m21, cmulc(u2,y1));
        m30 = cadd(m30, cmulc(u3,y0));
        m31 = cadd(m31, cmulc(u3,y1));
        m32 = cadd(m32, cmulc(u3,y2));
    }

    float tr4 = 0.25f*(d0+d1+d2+d3);
    float a0 = d0+tr4, a1 = d1+tr4, a2 = d2+tr4, a3 = d3+tr4;

    LDLf f;
    f.iD0 = 1.0f/a0;
    f.L10 = cscale(f.iD0, m10); f.L20 = cscale(f.iD0, m20); f.L30 = cscale(f.iD0, m30);
    float D1 = a1 - (m10.x*f.L10.x + m10.y*f.L10.y);
    f.iD1 = 1.0f/D1;
    float2 t21 = csub(m21, cmulc(m20, f.L10));
    f.L21 = cscale(f.iD1, t21);
    float2 t31 = csub(m31, cmulc(m30, f.L10));
    f.L31 = cscale(f.iD1, t31);
    float D2 = a2 - (m20.x*f.L20.x + m20.y*f.L20.y) - (t21.x*f.L21.x + t21.y*f.L21.y);
    f.iD2 = 1.0f/D2;
    float2 t32 = csub(csub(m32, cmulc(m30, f.L20)), cmulc(t31, f.L21));
    f.L32 = cscale(f.iD2, t32);
    float D3 = a3 - (m30.x*f.L30.x + m30.y*f.L30.y)
                  - (t31.x*f.L31.x + t31.y*f.L31.y)
                  - (t32.x*f.L32.x + t32.y*f.L32.y);
    f.iD3 = 1.0f/D3;

    const float phi = (float)(6.283185307179586 * 50.0 * 0.027 * 0.6427876096865393 / 340.0);
    float ang = phi * (float)k;
    float s1, c1; sincosf(ang, &s1, &c1);
    float c2 = c1*c1 - s1*s1, s2 = 2.f*c1*s1;
    float c3 = c2*c1 - s2*s1, s3 = s2*c1 + c2*s1;

    float2 one = make_float2(1.f, 0.f);
    float2 o1 = mvdr_beam(f, one, make_float2(c1,-s1), make_float2(c2,-s2), make_float2(c3,-s3),
                          X0, X1, X2, X3);
    float2 o2 = mvdr_beam(f, one, make_float2(c1, s1), make_float2(c2, s2), make_float2(c3, s3),
                          X0, X1, X2, X3);

    g_Y[((size_t)(0*B_+b)*F_ + k)*T_ + t] = o1;
    g_Y[((size_t)(1*B_+b)*F_ + k)*T_ + t] = o2;
}

// ---------------- ISTFT: 4 frames per block, inverse 16x20 DFT ----------------
__global__ void k_istft(){
    int tg = blockIdx.x, b = blockIdx.y, beam = blockIdx.z;
    int tid = threadIdx.x;
    __shared__ float2 sY[IT][F_];
    __shared__ float2 sH[IT][16][20];
    __shared__ float2 sWp[NFFT_];
    __shared__ float2 sW20[20];

    for(int i = tid; i < NFFT_; i += 256){
        float sn, cs; sincospif((float)i/160.0f, &sn, &cs);
        sWp[i] = make_float2(cs, sn);
    }
    if(tid < 20){
        float sn, cs; sincospif((float)tid/10.0f, &sn, &cs);
        sW20[tid] = make_float2(cs, sn);
    }
    // load: [beam][b][k][t] layout, groups of IT consecutive t per k -> 32B sectors
    size_t ybase = (size_t)(beam*B_+b)*F_*T_;
    for(int i = tid; i < F_*IT; i += 256){
        int k = i >> 2, j = i & 3;
        int t = tg*IT + j;
        if(t < T_) sY[j][k] = g_Y[ybase + (size_t)k*T_ + t];
    }
    __syncthreads();

    // stage A: H[k1][p] = sum_{k2<20} Z[16 k2 + k1] * W20^{k2 p}
    for(int task = tid; task < IT*NFFT_; task += 256){
        int j = task / NFFT_, r = task % NFFT_;
        if(tg*IT + j >= T_) continue;
        int k1 = r & 15, p = r >> 4;
        float2 acc = make_float2(0.f, 0.f);
        int idx = 0;
        #pragma unroll
        for(int k2 = 0; k2 < 20; k2++){
            int kk = 16*k2 + k1;
            float2 z;
            if(kk <= 160){
                z = sY[j][kk];
                if(kk == 0 || kk == 160) z.y = 0.f;
            } else {
                z = sY[j][320-kk]; z.y = -z.y;
            }
            float2 w = sW20[idx];
            acc.x += z.x*w.x - z.y*w.y;
            acc.y += z.x*w.y + z.y*w.x;
            idx += p; if(idx >= 20) idx -= 20;
        }
        sH[j][k1][p] = acc;
    }
    __syncthreads();

    // stage B: x[n] = (1/640) Re( sum_{k1<16} Wp^{k1 n} H[k1][n mod 20] )  (1/320 DFT * 1/2 OLA)
    for(int task = tid; task < IT*NFFT_; task += 256){
        int j = task / NFFT_, n = task % NFFT_;
        int t = tg*IT + j;
        if(t >= T_) continue;
        int pm = n % 20;
        float acc = 0.f;
        int idx = 0;
        #pragma unroll
        for(int k1 = 0; k1 < 16; k1++){
            float2 h = sH[k1 == 0 ? j : j][k1][pm];
            float2 w = sWp[idx];
            acc += w.x*h.x - w.y*h.y;
            idx += n; if(idx >= NFFT_) idx -= NFFT_;
        }
        g_fr[((size_t)(beam*B_+b)*T_ + t)*NFFT_ + n] = acc * (1.0f/640.0f);
    }
}

// ---------------- overlap-add ----------------
__global__ void k_ola(float* __restrict__ out){
    int idx = blockIdx.x*blockDim.x + threadIdx.x;
    if(idx >= 2*B_*L_) return;
    int bb = idx / L_;
    int l  = idx % L_;
    int q   = l/160 + 1;
    int rem = l - (q-1)*160;
    out[idx] = g_fr[((size_t)bb*T_ + q)*NFFT_ + rem]
             + g_fr[((size_t)bb*T_ + (q-1))*NFFT_ + rem + 160];
}

// ---------------- launch ----------------
extern "C" void kernel_launch(void* const* d_in, const int* in_sizes, int n_in,
                              void* d_out, int out_size){
    const float* x   = (const float*)d_in[0];
    const float* win = (const float*)d_in[1];
    float* out = (float*)d_out;

    k_stats<<<dim3(32, B_), 256>>>(x);
    k_stft <<<dim3(T_, B_), 256>>>(x, win);
    k_beam <<<dim3((T_+BT-1)/BT, B_, F_), BT>>>();
    k_istft<<<dim3((T_+IT-1)/IT, B_, 2), 256>>>();
    k_ola  <<<(2*B_*L_ + 255)/256, 256>>>(out);
}

// round 4
// speedup vs baseline: 2.9997x; 2.3209x over previous
#include <cuda_runtime.h>
#include <math.h>

#define B_    8
#define L_    160000
#define C_    4
#define NFFT_ 320
#define HOP_  160
#define T_    1001
#define F_    161
#define KTAP  10
#define BT    128        // beam t-tile
#define IT    4          // istft frames per block

// ---------------- scratch ----------------
__device__ float2 g_X [(size_t)B_*F_*T_*C_];    // STFT  [b][k][t][c]
__device__ float2 g_Y [(size_t)2*B_*F_*T_];     // beams [beam][b][k][t]
__device__ float  g_fr[(size_t)2*B_*T_*NFFT_];  // istft frames [beam*B+b][t][n]
__device__ float4 g_ssum[B_*32];
__device__ float4 g_smax[B_*32];
__device__ float4 g_smin[B_*32];

__constant__ float c_c95[KTAP] = {0.95f, 0.0475f, 2.375e-3f, 1.1875e-4f, 5.9375e-6f,
                                  2.96875e-7f, 1.484375e-8f, 7.421875e-10f,
                                  3.7109375e-11f, 1.85546875e-12f};
__constant__ float c_p05[KTAP] = {1.0f, 0.05f, 2.5e-3f, 1.25e-4f, 6.25e-6f,
                                  3.125e-7f, 1.5625e-8f, 7.8125e-10f,
                                  3.90625e-11f, 1.953125e-12f};

// ---------------- complex helpers ----------------
__device__ __forceinline__ float2 cadd(float2 a, float2 b){ return make_float2(a.x+b.x, a.y+b.y); }
__device__ __forceinline__ float2 csub(float2 a, float2 b){ return make_float2(a.x-b.x, a.y-b.y); }
__device__ __forceinline__ float2 cmul(float2 a, float2 b){ return make_float2(a.x*b.x-a.y*b.y, a.x*b.y+a.y*b.x); }
__device__ __forceinline__ float2 ccmul(float2 a, float2 b){ return make_float2(a.x*b.x+a.y*b.y, a.x*b.y-a.y*b.x); } // conj(a)*b
__device__ __forceinline__ float2 cmulc(float2 a, float2 b){ return make_float2(a.x*b.x+a.y*b.y, a.y*b.x-a.x*b.y); } // a*conj(b)
__device__ __forceinline__ float2 cscale(float s, float2 a){ return make_float2(s*a.x, s*a.y); }

// ---------------- single-pass stats: sum / max / min per (b, chunk) ----------------
__global__ void k_stats(const float* __restrict__ x){
    int b = blockIdx.y, ch = blockIdx.x;
    int l0 = ch*5000;
    float4 s  = make_float4(0.f,0.f,0.f,0.f);
    float4 mx = make_float4(-1e30f,-1e30f,-1e30f,-1e30f);
    float4 mn = make_float4( 1e30f, 1e30f, 1e30f, 1e30f);
    for(int l = l0 + threadIdx.x; l < l0+5000; l += 256){
        float4 v = *(const float4*)(x + ((size_t)b*L_ + l)*C_);
        s.x += v.x; s.y += v.y; s.z += v.z; s.w += v.w;
        mx.x = fmaxf(mx.x,v.x); mx.y = fmaxf(mx.y,v.y); mx.z = fmaxf(mx.z,v.z); mx.w = fmaxf(mx.w,v.w);
        mn.x = fminf(mn.x,v.x); mn.y = fminf(mn.y,v.y); mn.z = fminf(mn.z,v.z); mn.w = fminf(mn.w,v.w);
    }
    __shared__ float4 rs[256], rx[256], rn[256];
    rs[threadIdx.x]=s; rx[threadIdx.x]=mx; rn[threadIdx.x]=mn; __syncthreads();
    for(int st = 128; st > 0; st >>= 1){
        if(threadIdx.x < st){
            float4 o = rs[threadIdx.x+st];
            rs[threadIdx.x].x += o.x; rs[threadIdx.x].y += o.y; rs[threadIdx.x].z += o.z; rs[threadIdx.x].w += o.w;
            float4 a = rx[threadIdx.x+st];
            rx[threadIdx.x].x = fmaxf(rx[threadIdx.x].x,a.x); rx[threadIdx.x].y = fmaxf(rx[threadIdx.x].y,a.y);
            rx[threadIdx.x].z = fmaxf(rx[threadIdx.x].z,a.z); rx[threadIdx.x].w = fmaxf(rx[threadIdx.x].w,a.w);
            float4 c = rn[threadIdx.x+st];
            rn[threadIdx.x].x = fminf(rn[threadIdx.x].x,c.x); rn[threadIdx.x].y = fminf(rn[threadIdx.x].y,c.y);
            rn[threadIdx.x].z = fminf(rn[threadIdx.x].z,c.z); rn[threadIdx.x].w = fminf(rn[threadIdx.x].w,c.w);
        }
        __syncthreads();
    }
    if(threadIdx.x == 0){
        g_ssum[b*32+ch] = rs[0]; g_smax[b*32+ch] = rx[0]; g_smin[b*32+ch] = rn[0];
    }
}

// ---------------- STFT: fused stats-finalize + reflect-pad + normalize + window + 16x20 DFT ----------------
__global__ void k_stft(const float* __restrict__ x, const float* __restrict__ win){
    int t = blockIdx.x, b = blockIdx.y;
    int tid = threadIdx.x;
    __shared__ float  sv[C_][NFFT_];
    __shared__ float2 sG[C_][9][20];
    __shared__ float  sMean[4];
    __shared__ float  sInv;

    // finalize stats (warp 0)
    if(tid < 32){
        float4 s  = g_ssum[b*32+tid];
        float4 mx = g_smax[b*32+tid];
        float4 mn = g_smin[b*32+tid];
        for(int o = 16; o; o >>= 1){
            s.x += __shfl_xor_sync(~0u, s.x, o); s.y += __shfl_xor_sync(~0u, s.y, o);
            s.z += __shfl_xor_sync(~0u, s.z, o); s.w += __shfl_xor_sync(~0u, s.w, o);
            mx.x = fmaxf(mx.x, __shfl_xor_sync(~0u, mx.x, o)); mx.y = fmaxf(mx.y, __shfl_xor_sync(~0u, mx.y, o));
            mx.z = fmaxf(mx.z, __shfl_xor_sync(~0u, mx.z, o)); mx.w = fmaxf(mx.w, __shfl_xor_sync(~0u, mx.w, o));
            mn.x = fminf(mn.x, __shfl_xor_sync(~0u, mn.x, o)); mn.y = fminf(mn.y, __shfl_xor_sync(~0u, mn.y, o));
            mn.z = fminf(mn.z, __shfl_xor_sync(~0u, mn.z, o)); mn.w = fminf(mn.w, __shfl_xor_sync(~0u, mn.w, o));
        }
        if(tid == 0){
            float m0 = s.x/(float)L_, m1 = s.y/(float)L_, m2 = s.z/(float)L_, m3 = s.w/(float)L_;
            float a = fmaxf(fmaxf(mx.x-m0, m0-mn.x), fmaxf(mx.y-m1, m1-mn.y));
            a = fmaxf(a, fmaxf(fmaxf(mx.z-m2, m2-mn.z), fmaxf(mx.w-m3, m3-mn.w)));
            sMean[0]=m0; sMean[1]=m1; sMean[2]=m2; sMean[3]=m3; sInv = 1.0f/a;
        }
    }
    __syncthreads();

    float m0 = sMean[0], m1 = sMean[1], m2 = sMean[2], m3 = sMean[3], inv = sInv;
    for(int n = tid; n < NFFT_; n += 256){
        int l = t*HOP_ + n - (NFFT_/2);
        if(l < 0) l = -l;
        else if(l >= L_) l = 2*L_ - 2 - l;
        float4 v = *(const float4*)(x + ((size_t)b*L_ + l)*C_);
        float w = win[n] * inv;
        sv[0][n] = (v.x-m0)*w; sv[1][n] = (v.y-m1)*w; sv[2][n] = (v.z-m2)*w; sv[3][n] = (v.w-m3)*w;
    }
    __syncthreads();

    // stage 1: G[c][m][r] = sum_q v[20q+r] * W16^{-qm}, m=0..8 (incremental twiddle)
    for(int task = tid; task < C_*20*9; task += 256){
        int c = task/180, rm = task%180, r = rm/9, m = rm%9;
        float sn, cs; sincospif(-(float)m/8.0f, &sn, &cs);
        float2 wst = make_float2(cs, sn), w = make_float2(1.f, 0.f);
        float re = 0.f, im = 0.f;
        #pragma unroll
        for(int q = 0; q < 16; q++){
            float v = sv[c][20*q + r];
            re += v*w.x; im += v*w.y;
            w = cmul(w, wst);
        }
        sG[c][m][r] = make_float2(re, im);
    }
    __syncthreads();

    // stage 2: bins k and 160-k from one pass via even/odd-r accumulators
    for(int task = tid; task < 81*C_; task += 256){
        int k = task >> 2, c = task & 3;          // k in 0..80
        int m = k & 15;
        bool hi = (m > 8);
        int mm = hi ? 16-m : m;
        float sgn = hi ? -1.f : 1.f;
        float sn, cs; sincospif(-(float)k/160.0f, &sn, &cs);
        float2 wst = make_float2(cs, sn), w = make_float2(1.f, 0.f);
        float2 ae = make_float2(0.f,0.f), ao = make_float2(0.f,0.f);
        #pragma unroll
        for(int r = 0; r < 20; r++){
            float2 g = sG[c][mm][r]; g.y *= sgn;
            float2 mv = cmul(w, g);
            if(r & 1){ ao.x += mv.x; ao.y += mv.y; }
            else     { ae.x += mv.x; ae.y += mv.y; }
            w = cmul(w, wst);
        }
        g_X[(((size_t)b*F_ + k)*T_ + t)*C_ + c] = cadd(ae, ao);
        if(k != 80){
            float2 d = csub(ae, ao);
            g_X[(((size_t)b*F_ + (160-k))*T_ + t)*C_ + c] = make_float2(d.x, -d.y);
        }
    }
}

// ---------------- MVDR beam: t-tiled in shared, LDL^H solve ----------------
struct LDLf { float iD0,iD1,iD2,iD3; float2 L10,L20,L30,L21,L31,L32; };

__device__ __forceinline__ float2 mvdr_beam(const LDLf& f,
    float2 h0, float2 h1, float2 h2, float2 h3,
    float2 X0, float2 X1, float2 X2, float2 X3)
{
    float2 z0 = h0;
    float2 z1 = csub(h1, cmul(f.L10, z0));
    float2 z2 = csub(csub(h2, cmul(f.L20, z0)), cmul(f.L21, z1));
    float2 z3 = csub(csub(csub(h3, cmul(f.L30, z0)), cmul(f.L31, z1)), cmul(f.L32, z2));
    float2 u0 = cscale(f.iD0, z0), u1 = cscale(f.iD1, z1);
    float2 u2 = cscale(f.iD2, z2), u3 = cscale(f.iD3, z3);
    float2 y3 = u3;
    float2 y2 = csub(u2, ccmul(f.L32, y3));
    float2 y1 = csub(csub(u1, ccmul(f.L21, y2)), ccmul(f.L31, y3));
    float2 y0 = csub(csub(csub(u0, ccmul(f.L10, y1)), ccmul(f.L20, y2)), ccmul(f.L30, y3));
    float2 den = cadd(cadd(ccmul(h0,y0), ccmul(h1,y1)), cadd(ccmul(h2,y2), ccmul(h3,y3)));
    float2 s   = cadd(cadd(ccmul(y0,X0), ccmul(y1,X1)), cadd(ccmul(y2,X2), ccmul(y3,X3)));
    float inv = 1.0f/(den.x*den.x + den.y*den.y);
    float2 sd = cmul(s, den);
    return make_float2(sd.x*inv, sd.y*inv);
}

__global__ void k_beam(){
    int tb = blockIdx.x, b = blockIdx.y, k = blockIdx.z;
    int tid = threadIdx.x;
    __shared__ float4 sX[(BT + KTAP - 1)*2];

    int ts = tb*BT - (KTAP-1);
    const float4* gx = (const float4*)g_X + ((size_t)(b*F_ + k))*T_*2;
    for(int i = tid; i < (BT + KTAP - 1)*2; i += BT){
        int tt = ts + (i >> 1);
        if(tt >= 0 && tt < T_) sX[i] = gx[(size_t)tt*2 + (i & 1)];
    }
    __syncthreads();

    int t = tb*BT + tid;
    if(t >= T_) return;

    int base = (tid + KTAP - 1)*2;
    float4 xa = sX[base], xb = sX[base+1];
    float2 X0 = make_float2(xa.x,xa.y), X1 = make_float2(xa.z,xa.w);
    float2 X2 = make_float2(xb.x,xb.y), X3 = make_float2(xb.z,xb.w);

    float d0=0,d1=0,d2=0,d3=0;
    float2 m10={0,0}, m20={0,0}, m21={0,0}, m30={0,0}, m31={0,0}, m32={0,0};

    #pragma unroll
    for(int j = 0; j < KTAP; j++){
        int s = t - j;
        if(s < 0) break;
        float cf = (s == 0) ? c_p05[t] : c_c95[j];
        float2 y0,y1,y2,y3;
        if(j == 0){ y0=X0; y1=X1; y2=X2; y3=X3; }
        else{
            float4 a = sX[base - 2*j], bb = sX[base - 2*j + 1];
            y0 = make_float2(a.x,a.y); y1 = make_float2(a.z,a.w);
            y2 = make_float2(bb.x,bb.y); y3 = make_float2(bb.z,bb.w);
        }
        float2 u0 = cscale(cf,y0), u1 = cscale(cf,y1), u2 = cscale(cf,y2), u3 = cscale(cf,y3);
        d0 += u0.x*y0.x + u0.y*y0.y;
        d1 += u1.x*y1.x + u1.y*y1.y;
        d2 += u2.x*y2.x + u2.y*y2.y;
        d3 += u3.x*y3.x + u3.y*y3.y;
        m10 = cadd(m10, cmulc(u1,y0));
        m20 = cadd(m20, cmulc(u2,y0));
        m21 = cadd(m21, cmulc(u2,y1));
        m30 = cadd(m30, cmulc(u3,y0));
        m31 = cadd(m31, cmulc(u3,y1));
        m32 = cadd(m32, cmulc(u3,y2));
    }

    float tr4 = 0.25f*(d0+d1+d2+d3);
    float a0 = d0+tr4, a1 = d1+tr4, a2 = d2+tr4, a3 = d3+tr4;

    LDLf f;
    f.iD0 = 1.0f/a0;
    f.L10 = cscale(f.iD0, m10); f.L20 = cscale(f.iD0, m20); f.L30 = cscale(f.iD0, m30);
    float D1 = a1 - (m10.x*f.L10.x + m10.y*f.L10.y);
    f.iD1 = 1.0f/D1;
    float2 t21 = csub(m21, cmulc(m20, f.L10));
    f.L21 = cscale(f.iD1, t21);
    float2 t31 = csub(m31, cmulc(m30, f.L10));
    f.L31 = cscale(f.iD1, t31);
    float D2 = a2 - (m20.x*f.L20.x + m20.y*f.L20.y) - (t21.x*f.L21.x + t21.y*f.L21.y);
    f.iD2 = 1.0f/D2;
    float2 t32 = csub(csub(m32, cmulc(m30, f.L20)), cmulc(t31, f.L21));
    f.L32 = cscale(f.iD2, t32);
    float D3 = a3 - (m30.x*f.L30.x + m30.y*f.L30.y)
                  - (t31.x*f.L31.x + t31.y*f.L31.y)
                  - (t32.x*f.L32.x + t32.y*f.L32.y);
    f.iD3 = 1.0f/D3;

    const float phi = (float)(6.283185307179586 * 50.0 * 0.027 * 0.6427876096865393 / 340.0);
    float ang = phi * (float)k;
    float s1, c1; sincosf(ang, &s1, &c1);
    float c2 = c1*c1 - s1*s1, s2 = 2.f*c1*s1;
    float c3 = c2*c1 - s2*s1, s3 = s2*c1 + c2*s1;

    float2 one = make_float2(1.f, 0.f);
    float2 o1 = mvdr_beam(f, one, make_float2(c1,-s1), make_float2(c2,-s2), make_float2(c3,-s3),
                          X0, X1, X2, X3);
    float2 o2 = mvdr_beam(f, one, make_float2(c1, s1), make_float2(c2, s2), make_float2(c3, s3),
                          X0, X1, X2, X3);

    g_Y[((size_t)(0*B_+b)*F_ + k)*T_ + t] = o1;
    g_Y[((size_t)(1*B_+b)*F_ + k)*T_ + t] = o2;
}

// ---------------- ISTFT: Hermitian-folded inverse 16x20 DFT, 2 outputs/thread ----------------
__global__ void k_istft(){
    int tg = blockIdx.x, b = blockIdx.y, beam = blockIdx.z;
    int tid = threadIdx.x;
    __shared__ float2 sZ[IT][NFFT_];   // full conjugate-extended spectrum
    __shared__ float2 sH[IT][9][20];   // folded outer-stage results (k1=0..8, pre-scaled)

    // build sZ: [beam][b][k][t] layout; 4 consecutive t per kk -> 32B sectors
    size_t ybase = (size_t)(beam*B_+b)*F_*T_;
    for(int i = tid; i < IT*NFFT_; i += 256){
        int kk = i >> 2, j = i & 3;
        int t = tg*IT + j;
        if(t < T_){
            float2 z;
            if(kk <= 160){
                z = g_Y[ybase + (size_t)kk*T_ + t];
                if(kk == 0 || kk == 160) z.y = 0.f;
            } else {
                z = g_Y[ybase + (size_t)(320-kk)*T_ + t];
                z.y = -z.y;
            }
            sZ[j][kk] = z;
        }
    }
    __syncthreads();

    // stage A: H[k1][p], k1=0..8, p-pair (p, p+10) via even/odd-k2 accumulators
    for(int task = tid; task < IT*90; task += 256){
        int j = task/90, r = task%90, k1 = r/10, p = r%10;
        if(tg*IT + j >= T_) continue;
        float sn, cs; sincospif((float)p/10.0f, &sn, &cs);
        float2 wst = make_float2(cs, sn), w = make_float2(1.f, 0.f);
        float2 ae = make_float2(0.f,0.f), ao = make_float2(0.f,0.f);
        #pragma unroll
        for(int k2 = 0; k2 < 20; k2++){
            float2 z = sZ[j][16*k2 + k1];
            float2 mv = cmul(z, w);
            if(k2 & 1){ ao.x += mv.x; ao.y += mv.y; }
            else      { ae.x += mv.x; ae.y += mv.y; }
            w = cmul(w, wst);
        }
        float sc = (k1 == 0 || k1 == 8) ? 1.f : 2.f;   // Hermitian pairing weight
        sH[j][k1][p]    = cscale(sc, cadd(ae, ao));
        sH[j][k1][p+10] = cscale(sc, csub(ae, ao));
    }
    __syncthreads();

    // stage B: x[n], x[n+160] from 9 folded terms (even/odd-k1 accumulators)
    for(int task = tid; task < IT*160; task += 256){
        int j = task/160, n = task%160;
        int t = tg*IT + j;
        if(t >= T_) continue;
        int pm = n % 20;
        float sn, cs; sincospif((float)n/160.0f, &sn, &cs);
        float2 wst = make_float2(cs, sn), w = make_float2(1.f, 0.f);
        float e = 0.f, o = 0.f;
        #pragma unroll
        for(int k1 = 0; k1 < 9; k1++){
            float2 h = sH[j][k1][pm];
            float tr = w.x*h.x - w.y*h.y;
            if(k1 & 1) o += tr; else e += tr;
            w = cmul(w, wst);
        }
        float* pf = &g_fr[((size_t)(beam*B_+b)*T_ + t)*NFFT_];
        pf[n]       = (e + o) * (1.0f/640.0f);
        pf[n + 160] = (e - o) * (1.0f/640.0f);
    }
}

// ---------------- overlap-add ----------------
__global__ void k_ola(float* __restrict__ out){
    int idx = blockIdx.x*blockDim.x + threadIdx.x;
    if(idx >= 2*B_*L_) return;
    int bb = idx / L_;
    int l  = idx % L_;
    int q   = l/160 + 1;
    int rem = l - (q-1)*160;
    out[idx] = g_fr[((size_t)bb*T_ + q)*NFFT_ + rem]
             + g_fr[((size_t)bb*T_ + (q-1))*NFFT_ + rem + 160];
}

// ---------------- launch ----------------
extern "C" void kernel_launch(void* const* d_in, const int* in_sizes, int n_in,
                              void* d_out, int out_size){
    const float* x   = (const float*)d_in[0];
    const float* win = (const float*)d_in[1];
    float* out = (float*)d_out;

    k_stats<<<dim3(32, B_), 256>>>(x);
    k_stft <<<dim3(T_, B_), 256>>>(x, win);
    k_beam <<<dim3((T_+BT-1)/BT, B_, F_), BT>>>();
    k_istft<<<dim3((T_+IT-1)/IT, B_, 2), 256>>>();
    k_ola  <<<(2*B_*L_ + 255)/256, 256>>>(out);
}

// round 5
// speedup vs baseline: 3.8773x; 1.2926x over previous
#include <cuda_runtime.h>
#include <math.h>

#define B_    8
#define L_    160000
#define C_    4
#define NFFT_ 320
#define HOP_  160
#define T_    1001
#define F_    161
#define KTAP  6
#define BT    128        // beam t-tile
#define NQ    15         // istft: output q-segments per block
#define TF    16         // istft: frames per block (NQ+1)

// ---------------- scratch ----------------
__device__ float2 g_X [(size_t)B_*F_*T_*C_];    // STFT  [b][k][t][c]
__device__ float2 g_Y [(size_t)2*B_*F_*T_];     // beams [beam][b][k][t]
__device__ float4 g_ssum[B_*32];
__device__ float4 g_smax[B_*32];
__device__ float4 g_smin[B_*32];

__constant__ float c_c95[10] = {0.95f, 0.0475f, 2.375e-3f, 1.1875e-4f, 5.9375e-6f,
                                2.96875e-7f, 1.484375e-8f, 7.421875e-10f,
                                3.7109375e-11f, 1.85546875e-12f};
__constant__ float c_p05[10] = {1.0f, 0.05f, 2.5e-3f, 1.25e-4f, 6.25e-6f,
                                3.125e-7f, 1.5625e-8f, 7.8125e-10f,
                                3.90625e-11f, 1.953125e-12f};

// ---------------- complex helpers ----------------
__device__ __forceinline__ float2 cadd(float2 a, float2 b){ return make_float2(a.x+b.x, a.y+b.y); }
__device__ __forceinline__ float2 csub(float2 a, float2 b){ return make_float2(a.x-b.x, a.y-b.y); }
__device__ __forceinline__ float2 cmul(float2 a, float2 b){ return make_float2(a.x*b.x-a.y*b.y, a.x*b.y+a.y*b.x); }
__device__ __forceinline__ float2 ccmul(float2 a, float2 b){ return make_float2(a.x*b.x+a.y*b.y, a.x*b.y-a.y*b.x); } // conj(a)*b
__device__ __forceinline__ float2 cmulc(float2 a, float2 b){ return make_float2(a.x*b.x+a.y*b.y, a.y*b.x-a.x*b.y); } // a*conj(b)
__device__ __forceinline__ float2 cscale(float s, float2 a){ return make_float2(s*a.x, s*a.y); }

// ---------------- single-pass stats: sum / max / min per (b, chunk) ----------------
__global__ void k_stats(const float* __restrict__ x){
    int b = blockIdx.y, ch = blockIdx.x;
    int l0 = ch*5000;
    float4 s  = make_float4(0.f,0.f,0.f,0.f);
    float4 mx = make_float4(-1e30f,-1e30f,-1e30f,-1e30f);
    float4 mn = make_float4( 1e30f, 1e30f, 1e30f, 1e30f);
    for(int l = l0 + threadIdx.x; l < l0+5000; l += 256){
        float4 v = *(const float4*)(x + ((size_t)b*L_ + l)*C_);
        s.x += v.x; s.y += v.y; s.z += v.z; s.w += v.w;
        mx.x = fmaxf(mx.x,v.x); mx.y = fmaxf(mx.y,v.y); mx.z = fmaxf(mx.z,v.z); mx.w = fmaxf(mx.w,v.w);
        mn.x = fminf(mn.x,v.x); mn.y = fminf(mn.y,v.y); mn.z = fminf(mn.z,v.z); mn.w = fminf(mn.w,v.w);
    }
    __shared__ float4 rs[256], rx[256], rn[256];
    rs[threadIdx.x]=s; rx[threadIdx.x]=mx; rn[threadIdx.x]=mn; __syncthreads();
    for(int st = 128; st > 0; st >>= 1){
        if(threadIdx.x < st){
            float4 o = rs[threadIdx.x+st];
            rs[threadIdx.x].x += o.x; rs[threadIdx.x].y += o.y; rs[threadIdx.x].z += o.z; rs[threadIdx.x].w += o.w;
            float4 a = rx[threadIdx.x+st];
            rx[threadIdx.x].x = fmaxf(rx[threadIdx.x].x,a.x); rx[threadIdx.x].y = fmaxf(rx[threadIdx.x].y,a.y);
            rx[threadIdx.x].z = fmaxf(rx[threadIdx.x].z,a.z); rx[threadIdx.x].w = fmaxf(rx[threadIdx.x].w,a.w);
            float4 c = rn[threadIdx.x+st];
            rn[threadIdx.x].x = fminf(rn[threadIdx.x].x,c.x); rn[threadIdx.x].y = fminf(rn[threadIdx.x].y,c.y);
            rn[threadIdx.x].z = fminf(rn[threadIdx.x].z,c.z); rn[threadIdx.x].w = fminf(rn[threadIdx.x].w,c.w);
        }
        __syncthreads();
    }
    if(threadIdx.x == 0){
        g_ssum[b*32+ch] = rs[0]; g_smax[b*32+ch] = rx[0]; g_smin[b*32+ch] = rn[0];
    }
}

// ---------------- STFT: fused stats-finalize + reflect-pad + normalize + window + 16x20 DFT ----------------
__global__ void k_stft(const float* __restrict__ x, const float* __restrict__ win){
    int t = blockIdx.x, b = blockIdx.y;
    int tid = threadIdx.x;
    __shared__ float  sv[C_][NFFT_];
    __shared__ float2 sG[C_][9][20];
    __shared__ float  sMean[4];
    __shared__ float  sInv;

    if(tid < 32){
        float4 s  = g_ssum[b*32+tid];
        float4 mx = g_smax[b*32+tid];
        float4 mn = g_smin[b*32+tid];
        for(int o = 16; o; o >>= 1){
            s.x += __shfl_xor_sync(~0u, s.x, o); s.y += __shfl_xor_sync(~0u, s.y, o);
            s.z += __shfl_xor_sync(~0u, s.z, o); s.w += __shfl_xor_sync(~0u, s.w, o);
            mx.x = fmaxf(mx.x, __shfl_xor_sync(~0u, mx.x, o)); mx.y = fmaxf(mx.y, __shfl_xor_sync(~0u, mx.y, o));
            mx.z = fmaxf(mx.z, __shfl_xor_sync(~0u, mx.z, o)); mx.w = fmaxf(mx.w, __shfl_xor_sync(~0u, mx.w, o));
            mn.x = fminf(mn.x, __shfl_xor_sync(~0u, mn.x, o)); mn.y = fminf(mn.y, __shfl_xor_sync(~0u, mn.y, o));
            mn.z = fminf(mn.z, __shfl_xor_sync(~0u, mn.z, o)); mn.w = fminf(mn.w, __shfl_xor_sync(~0u, mn.w, o));
        }
        if(tid == 0){
            float m0 = s.x/(float)L_, m1 = s.y/(float)L_, m2 = s.z/(float)L_, m3 = s.w/(float)L_;
            float a = fmaxf(fmaxf(mx.x-m0, m0-mn.x), fmaxf(mx.y-m1, m1-mn.y));
            a = fmaxf(a, fmaxf(fmaxf(mx.z-m2, m2-mn.z), fmaxf(mx.w-m3, m3-mn.w)));
            sMean[0]=m0; sMean[1]=m1; sMean[2]=m2; sMean[3]=m3; sInv = 1.0f/a;
        }
    }
    __syncthreads();

    float m0 = sMean[0], m1 = sMean[1], m2 = sMean[2], m3 = sMean[3], inv = sInv;
    for(int n = tid; n < NFFT_; n += 256){
        int l = t*HOP_ + n - (NFFT_/2);
        if(l < 0) l = -l;
        else if(l >= L_) l = 2*L_ - 2 - l;
        float4 v = *(const float4*)(x + ((size_t)b*L_ + l)*C_);
        float w = win[n] * inv;
        sv[0][n] = (v.x-m0)*w; sv[1][n] = (v.y-m1)*w; sv[2][n] = (v.z-m2)*w; sv[3][n] = (v.w-m3)*w;
    }
    __syncthreads();

    for(int task = tid; task < C_*20*9; task += 256){
        int c = task/180, rm = task%180, r = rm/9, m = rm%9;
        float sn, cs; sincospif(-(float)m/8.0f, &sn, &cs);
        float2 wst = make_float2(cs, sn), w = make_float2(1.f, 0.f);
        float re = 0.f, im = 0.f;
        #pragma unroll
        for(int q = 0; q < 16; q++){
            float v = sv[c][20*q + r];
            re += v*w.x; im += v*w.y;
            w = cmul(w, wst);
        }
        sG[c][m][r] = make_float2(re, im);
    }
    __syncthreads();

    for(int task = tid; task < 81*C_; task += 256){
        int k = task >> 2, c = task & 3;
        int m = k & 15;
        bool hi = (m > 8);
        int mm = hi ? 16-m : m;
        float sgn = hi ? -1.f : 1.f;
        float sn, cs; sincospif(-(float)k/160.0f, &sn, &cs);
        float2 wst = make_float2(cs, sn), w = make_float2(1.f, 0.f);
        float2 ae = make_float2(0.f,0.f), ao = make_float2(0.f,0.f);
        #pragma unroll
        for(int r = 0; r < 20; r++){
            float2 g = sG[c][mm][r]; g.y *= sgn;
            float2 mv = cmul(w, g);
            if(r & 1){ ao.x += mv.x; ao.y += mv.y; }
            else     { ae.x += mv.x; ae.y += mv.y; }
            w = cmul(w, wst);
        }
        g_X[(((size_t)b*F_ + k)*T_ + t)*C_ + c] = cadd(ae, ao);
        if(k != 80){
            float2 d = csub(ae, ao);
            g_X[(((size_t)b*F_ + (160-k))*T_ + t)*C_ + c] = make_float2(d.x, -d.y);
        }
    }
}

// ---------------- MVDR beam: t-tiled in shared, LDL^H solve ----------------
struct LDLf { float iD0,iD1,iD2,iD3; float2 L10,L20,L30,L21,L31,L32; };

__device__ __forceinline__ float2 mvdr_beam(const LDLf& f,
    float2 h0, float2 h1, float2 h2, float2 h3,
    float2 X0, float2 X1, float2 X2, float2 X3)
{
    float2 z0 = h0;
    float2 z1 = csub(h1, cmul(f.L10, z0));
    float2 z2 = csub(csub(h2, cmul(f.L20, z0)), cmul(f.L21, z1));
    float2 z3 = csub(csub(csub(h3, cmul(f.L30, z0)), cmul(f.L31, z1)), cmul(f.L32, z2));
    float2 u0 = cscale(f.iD0, z0), u1 = cscale(f.iD1, z1);
    float2 u2 = cscale(f.iD2, z2), u3 = cscale(f.iD3, z3);
    float2 y3 = u3;
    float2 y2 = csub(u2, ccmul(f.L32, y3));
    float2 y1 = csub(csub(u1, ccmul(f.L21, y2)), ccmul(f.L31, y3));
    float2 y0 = csub(csub(csub(u0, ccmul(f.L10, y1)), ccmul(f.L20, y2)), ccmul(f.L30, y3));
    float2 den = cadd(cadd(ccmul(h0,y0), ccmul(h1,y1)), cadd(ccmul(h2,y2), ccmul(h3,y3)));
    float2 s   = cadd(cadd(ccmul(y0,X0), ccmul(y1,X1)), cadd(ccmul(y2,X2), ccmul(y3,X3)));
    float inv = 1.0f/(den.x*den.x + den.y*den.y);
    float2 sd = cmul(s, den);
    return make_float2(sd.x*inv, sd.y*inv);
}

__global__ void k_beam(){
    int tb = blockIdx.x, b = blockIdx.y, k = blockIdx.z;
    int tid = threadIdx.x;
    __shared__ float4 sX[(BT + KTAP - 1)*2];

    int ts = tb*BT - (KTAP-1);
    const float4* gx = (const float4*)g_X + ((size_t)(b*F_ + k))*T_*2;
    for(int i = tid; i < (BT + KTAP - 1)*2; i += BT){
        int tt = ts + (i >> 1);
        if(tt >= 0 && tt < T_) sX[i] = gx[(size_t)tt*2 + (i & 1)];
    }
    __syncthreads();

    int t = tb*BT + tid;
    if(t >= T_) return;

    int base = (tid + KTAP - 1)*2;
    float4 xa = sX[base], xb = sX[base+1];
    float2 X0 = make_float2(xa.x,xa.y), X1 = make_float2(xa.z,xa.w);
    float2 X2 = make_float2(xb.x,xb.y), X3 = make_float2(xb.z,xb.w);

    float d0=0,d1=0,d2=0,d3=0;
    float2 m10={0,0}, m20={0,0}, m21={0,0}, m30={0,0}, m31={0,0}, m32={0,0};

    #pragma unroll
    for(int j = 0; j < KTAP; j++){
        int s = t - j;
        if(s < 0) break;
        float cf = (s == 0) ? c_p05[t] : c_c95[j];
        float2 y0,y1,y2,y3;
        if(j == 0){ y0=X0; y1=X1; y2=X2; y3=X3; }
        else{
            float4 a = sX[base - 2*j], bb = sX[base - 2*j + 1];
            y0 = make_float2(a.x,a.y); y1 = make_float2(a.z,a.w);
            y2 = make_float2(bb.x,bb.y); y3 = make_float2(bb.z,bb.w);
        }
        float2 u0 = cscale(cf,y0), u1 = cscale(cf,y1), u2 = cscale(cf,y2), u3 = cscale(cf,y3);
        d0 += u0.x*y0.x + u0.y*y0.y;
        d1 += u1.x*y1.x + u1.y*y1.y;
        d2 += u2.x*y2.x + u2.y*y2.y;
        d3 += u3.x*y3.x + u3.y*y3.y;
        m10 = cadd(m10, cmulc(u1,y0));
        m20 = cadd(m20, cmulc(u2,y0));
        m21 = cadd(m21, cmulc(u2,y1));
        m30 = cadd(m30, cmulc(u3,y0));
        m31 = cadd(m31, cmulc(u3,y1));
        m32 = cadd(m32, cmulc(u3,y2));
    }

    float tr4 = 0.25f*(d0+d1+d2+d3);
    float a0 = d0+tr4, a1 = d1+tr4, a2 = d2+tr4, a3 = d3+tr4;

    LDLf f;
    f.iD0 = 1.0f/a0;
    f.L10 = cscale(f.iD0, m10); f.L20 = cscale(f.iD0, m20); f.L30 = cscale(f.iD0, m30);
    float D1 = a1 - (m10.x*f.L10.x + m10.y*f.L10.y);
    f.iD1 = 1.0f/D1;
    float2 t21 = csub(m21, cmulc(m20, f.L10));
    f.L21 = cscale(f.iD1, t21);
    float2 t31 = csub(m31, cmulc(m30, f.L10));
    f.L31 = cscale(f.iD1, t31);
    float D2 = a2 - (m20.x*f.L20.x + m20.y*f.L20.y) - (t21.x*f.L21.x + t21.y*f.L21.y);
    f.iD2 = 1.0f/D2;
    float2 t32 = csub(csub(m32, cmulc(m30, f.L20)), cmulc(t31, f.L21));
    f.L32 = cscale(f.iD2, t32);
    float D3 = a3 - (m30.x*f.L30.x + m30.y*f.L30.y)
                  - (t31.x*f.L31.x + t31.y*f.L31.y)
                  - (t32.x*f.L32.x + t32.y*f.L32.y);
    f.iD3 = 1.0f/D3;

    const float phi = (float)(6.283185307179586 * 50.0 * 0.027 * 0.6427876096865393 / 340.0);
    float ang = phi * (float)k;
    float s1, c1; sincosf(ang, &s1, &c1);
    float c2 = c1*c1 - s1*s1, s2 = 2.f*c1*s1;
    float c3 = c2*c1 - s2*s1, s3 = s2*c1 + c2*s1;

    float2 one = make_float2(1.f, 0.f);
    float2 o1 = mvdr_beam(f, one, make_float2(c1,-s1), make_float2(c2,-s2), make_float2(c3,-s3),
                          X0, X1, X2, X3);
    float2 o2 = mvdr_beam(f, one, make_float2(c1, s1), make_float2(c2, s2), make_float2(c3, s3),
                          X0, X1, X2, X3);

    g_Y[((size_t)(0*B_+b)*F_ + k)*T_ + t] = o1;
    g_Y[((size_t)(1*B_+b)*F_ + k)*T_ + t] = o2;
}

// ---------------- ISTFT + OLA fused: register radix DFT-20, constant-twiddle DFT-16 ----------------
__global__ void k_istft(float* __restrict__ out){
    // compile-time twiddle tables (folded to immediates in unrolled loops)
    const float C20[20] = { 1.f, 0.9510565163f, 0.8090169944f, 0.5877852523f, 0.3090169944f,
                            0.f,-0.3090169944f,-0.5877852523f,-0.8090169944f,-0.9510565163f,
                           -1.f,-0.9510565163f,-0.8090169944f,-0.5877852523f,-0.3090169944f,
                            0.f, 0.3090169944f, 0.5877852523f, 0.8090169944f, 0.9510565163f };
    const float S20[20] = { 0.f, 0.3090169944f, 0.5877852523f, 0.8090169944f, 0.9510565163f,
                            1.f, 0.9510565163f, 0.8090169944f, 0.5877852523f, 0.3090169944f,
                            0.f,-0.3090169944f,-0.5877852523f,-0.8090169944f,-0.9510565163f,
                           -1.f,-0.9510565163f,-0.8090169944f,-0.5877852523f,-0.3090169944f };
    const float C16[16] = { 1.f, 0.9238795325f, 0.7071067812f, 0.3826834324f, 0.f,
                           -0.3826834324f,-0.7071067812f,-0.9238795325f,-1.f,-0.9238795325f,
                           -0.7071067812f,-0.3826834324f, 0.f, 0.3826834324f, 0.7071067812f, 0.9238795325f };
    const float S16[16] = { 0.f, 0.3826834324f, 0.7071067812f, 0.9238795325f, 1.f,
                            0.9238795325f, 0.7071067812f, 0.3826834324f, 0.f,-0.3826834324f,
                           -0.7071067812f,-0.9238795325f,-1.f,-0.9238795325f,-0.7071067812f,-0.3826834324f };

    int blk = blockIdx.x, b = blockIdx.y, beam = blockIdx.z;
    int tid = threadIdx.x;          // 0..287
    int t0  = blk*NQ;               // first frame of tile
    __shared__ float2 sH[9][20][TF+1];   // [k1][p][f]
    __shared__ float  sFr[TF][322];      // frames (padded: stride 322 -> conflict-free)

    size_t ybase = (size_t)(beam*B_+b)*F_*T_;

    // ---- stage A: per (k1, frame) inverse DFT-20 in registers (CT 4x5, constant twiddles) ----
    {
        int k1 = tid >> 4;          // 0..17; active 0..8
        int f  = tid & 15;
        if(k1 < 9){
            int t = t0 + f;
            float2 z[20];
            if(t < T_){
                #pragma unroll
                for(int k2 = 0; k2 < 20; k2++){
                    int kk = 16*k2 + k1;
                    float2 v;
                    if(kk <= 160){
                        v = g_Y[ybase + (size_t)kk*T_ + t];
                        if(k1 == 0 && (k2 == 0 || k2 == 10)) v.y = 0.f;
                    } else {
                        v = g_Y[ybase + (size_t)(320-kk)*T_ + t];
                        v.y = -v.y;
                    }
                    z[k2] = v;
                }
            } else {
                #pragma unroll
                for(int k2 = 0; k2 < 20; k2++) z[k2] = make_float2(0.f,0.f);
            }
            // inner DFT-4 over a (W4 = +i), for each residue bq
            float2 Y[5][4];
            #pragma unroll
            for(int bq = 0; bq < 5; bq++){
                float2 z0=z[bq], z1=z[bq+5], z2=z[bq+10], z3=z[bq+15];
                float2 s0=cadd(z0,z2), s1=csub(z0,z2), s2=cadd(z1,z3), s3=csub(z1,z3);
                Y[bq][0] = cadd(s0,s2);
                Y[bq][2] = csub(s0,s2);
                Y[bq][1] = make_float2(s1.x - s3.y, s1.y + s3.x);
                Y[bq][3] = make_float2(s1.x + s3.y, s1.y - s3.x);
            }
            float sc = (k1==0 || k1==8) ? 1.f : 2.f;   // Hermitian fold weight
            #pragma unroll
            for(int p = 0; p < 20; p++){
                float2 acc = Y[0][p&3];
                #pragma unroll
                for(int bq = 1; bq < 5; bq++){
                    float cw = C20[(bq*p)%20], sw = S20[(bq*p)%20];
                    float2 y = Y[bq][p&3];
                    acc.x += cw*y.x - sw*y.y;
                    acc.y += cw*y.y + sw*y.x;
                }
                sH[k1][p][f] = make_float2(sc*acc.x, sc*acc.y);
            }
        }
    }
    __syncthreads();

    // ---- stage B: per (pm, frame): twiddle + 9-term constant DFT-16 -> 16 samples ----
    for(int task = tid; task < 20*TF; task += 288){
        int pm = task >> 4;
        int f  = task & 15;
        float sn, cs; sincospif((float)pm/160.0f, &sn, &cs);  // e^{+2pi i pm/320}
        float2 wst = make_float2(cs, sn), w = make_float2(1.f, 0.f);
        float2 a[9];
        a[0] = sH[0][pm][f];
        #pragma unroll
        for(int k1 = 1; k1 < 9; k1++){
            w = cmul(w, wst);
            a[k1] = cmul(sH[k1][pm][f], w);
        }
        #pragma unroll
        for(int u = 0; u < 16; u++){
            float acc = a[0].x;
            #pragma unroll
            for(int k1 = 1; k1 < 9; k1++){
                int j = (k1*u) & 15;
                acc += a[k1].x*C16[j] - a[k1].y*S16[j];
            }
            sFr[f][20*u + pm] = acc * (1.0f/640.0f);
        }
    }
    __syncthreads();

    // ---- output: OLA of adjacent frames, coalesced float2 stores ----
    int qmax = min(t0 + NQ, T_ - 1);       // q in [t0+1, qmax]
    int nq = qmax - t0;
    float* po = out + (size_t)(beam*B_+b)*L_;
    for(int task = tid; task < nq*80; task += 288){
        int qi = task / 80;
        int rr = (task - qi*80)*2;
        int q  = t0 + 1 + qi;
        int fq = qi + 1;
        float v0 = sFr[fq][rr]   + sFr[fq-1][160+rr];
        float v1 = sFr[fq][rr+1] + sFr[fq-1][161+rr];
        *(float2*)(po + (size_t)(q-1)*160 + rr) = make_float2(v0, v1);
    }
}

// ---------------- launch ----------------
extern "C" void kernel_launch(void* const* d_in, const int* in_sizes, int n_in,
                              void* d_out, int out_size){
    const float* x   = (const float*)d_in[0];
    const float* win = (const float*)d_in[1];
    float* out = (float*)d_out;

    k_stats<<<dim3(32, B_), 256>>>(x);
    k_stft <<<dim3(T_, B_), 256>>>(x, win);
    k_beam <<<dim3((T_+BT-1)/BT, B_, F_), BT>>>();
    k_istft<<<dim3((T_-1+NQ-1)/NQ, B_, 2), 288>>>(out);
}

// round 6
// speedup vs baseline: 5.7232x; 1.4761x over previous
#include <cuda_runtime.h>
#include <math.h>

#define B_    8
#define L_    160000
#define C_    4
#define NFFT_ 320
#define HOP_  160
#define T_    1001
#define F_    161
#define KTAP  6
#define BT    128        // beam t-tile
#define NQ    15         // istft: output q-segments per block
#define TF    16         // istft: frames per block (NQ+1)
#define TS4   4          // stft: frames per block
#define SVLEN (160*TS4 + 160)   // 800

// ---------------- scratch ----------------
__device__ float2 g_X [(size_t)B_*F_*T_*C_];    // STFT  [b][k][t][c]
__device__ float2 g_Y [(size_t)2*B_*F_*T_];     // beams [beam][b][k][t]
__device__ float4 g_ssum[B_*32];
__device__ float4 g_smax[B_*32];
__device__ float4 g_smin[B_*32];

__constant__ float c_c95[10] = {0.95f, 0.0475f, 2.375e-3f, 1.1875e-4f, 5.9375e-6f,
                                2.96875e-7f, 1.484375e-8f, 7.421875e-10f,
                                3.7109375e-11f, 1.85546875e-12f};
__constant__ float c_p05[10] = {1.0f, 0.05f, 2.5e-3f, 1.25e-4f, 6.25e-6f,
                                3.125e-7f, 1.5625e-8f, 7.8125e-10f,
                                3.90625e-11f, 1.953125e-12f};

// ---------------- complex helpers ----------------
__device__ __forceinline__ float2 cadd(float2 a, float2 b){ return make_float2(a.x+b.x, a.y+b.y); }
__device__ __forceinline__ float2 csub(float2 a, float2 b){ return make_float2(a.x-b.x, a.y-b.y); }
__device__ __forceinline__ float2 cmul(float2 a, float2 b){ return make_float2(a.x*b.x-a.y*b.y, a.x*b.y+a.y*b.x); }
__device__ __forceinline__ float2 ccmul(float2 a, float2 b){ return make_float2(a.x*b.x+a.y*b.y, a.x*b.y-a.y*b.x); } // conj(a)*b
__device__ __forceinline__ float2 cmulc(float2 a, float2 b){ return make_float2(a.x*b.x+a.y*b.y, a.y*b.x-a.x*b.y); } // a*conj(b)
__device__ __forceinline__ float2 cscale(float s, float2 a){ return make_float2(s*a.x, s*a.y); }

// ---------------- single-pass stats ----------------
__global__ void k_stats(const float* __restrict__ x){
    int b = blockIdx.y, ch = blockIdx.x;
    int l0 = ch*5000;
    float4 s  = make_float4(0.f,0.f,0.f,0.f);
    float4 mx = make_float4(-1e30f,-1e30f,-1e30f,-1e30f);
    float4 mn = make_float4( 1e30f, 1e30f, 1e30f, 1e30f);
    for(int l = l0 + threadIdx.x; l < l0+5000; l += 256){
        float4 v = *(const float4*)(x + ((size_t)b*L_ + l)*C_);
        s.x += v.x; s.y += v.y; s.z += v.z; s.w += v.w;
        mx.x = fmaxf(mx.x,v.x); mx.y = fmaxf(mx.y,v.y); mx.z = fmaxf(mx.z,v.z); mx.w = fmaxf(mx.w,v.w);
        mn.x = fminf(mn.x,v.x); mn.y = fminf(mn.y,v.y); mn.z = fminf(mn.z,v.z); mn.w = fminf(mn.w,v.w);
    }
    __shared__ float4 rs[256], rx[256], rn[256];
    rs[threadIdx.x]=s; rx[threadIdx.x]=mx; rn[threadIdx.x]=mn; __syncthreads();
    for(int st = 128; st > 0; st >>= 1){
        if(threadIdx.x < st){
            float4 o = rs[threadIdx.x+st];
            rs[threadIdx.x].x += o.x; rs[threadIdx.x].y += o.y; rs[threadIdx.x].z += o.z; rs[threadIdx.x].w += o.w;
            float4 a = rx[threadIdx.x+st];
            rx[threadIdx.x].x = fmaxf(rx[threadIdx.x].x,a.x); rx[threadIdx.x].y = fmaxf(rx[threadIdx.x].y,a.y);
            rx[threadIdx.x].z = fmaxf(rx[threadIdx.x].z,a.z); rx[threadIdx.x].w = fmaxf(rx[threadIdx.x].w,a.w);
            float4 c = rn[threadIdx.x+st];
            rn[threadIdx.x].x = fminf(rn[threadIdx.x].x,c.x); rn[threadIdx.x].y = fminf(rn[threadIdx.x].y,c.y);
            rn[threadIdx.x].z = fminf(rn[threadIdx.x].z,c.z); rn[threadIdx.x].w = fminf(rn[threadIdx.x].w,c.w);
        }
        __syncthreads();
    }
    if(threadIdx.x == 0){
        g_ssum[b*32+ch] = rs[0]; g_smax[b*32+ch] = rx[0]; g_smin[b*32+ch] = rn[0];
    }
}

// ---------------- STFT: 4 frames/block, register radix DFT-16 + constant DFT-20 ----------------
__global__ void k_stft(const float* __restrict__ x, const float* __restrict__ win){
    // constant twiddle tables (positive sin; negative-exponent applied in formulas)
    const float C16[16] = { 1.f, 0.9238795325f, 0.7071067812f, 0.3826834324f, 0.f,
                           -0.3826834324f,-0.7071067812f,-0.9238795325f,-1.f,-0.9238795325f,
                           -0.7071067812f,-0.3826834324f, 0.f, 0.3826834324f, 0.7071067812f, 0.9238795325f };
    const float S16[16] = { 0.f, 0.3826834324f, 0.7071067812f, 0.9238795325f, 1.f,
                            0.9238795325f, 0.7071067812f, 0.3826834324f, 0.f,-0.3826834324f,
                           -0.7071067812f,-0.9238795325f,-1.f,-0.9238795325f,-0.7071067812f,-0.3826834324f };
    const float C20[20] = { 1.f, 0.9510565163f, 0.8090169944f, 0.5877852523f, 0.3090169944f,
                            0.f,-0.3090169944f,-0.5877852523f,-0.8090169944f,-0.9510565163f,
                           -1.f,-0.9510565163f,-0.8090169944f,-0.5877852523f,-0.3090169944f,
                            0.f, 0.3090169944f, 0.5877852523f, 0.8090169944f, 0.9510565163f };
    const float S20[20] = { 0.f, 0.3090169944f, 0.5877852523f, 0.8090169944f, 0.9510565163f,
                            1.f, 0.9510565163f, 0.8090169944f, 0.5877852523f, 0.3090169944f,
                            0.f,-0.3090169944f,-0.5877852523f,-0.8090169944f,-0.9510565163f,
                           -1.f,-0.9510565163f,-0.8090169944f,-0.5877852523f,-0.3090169944f };

    int blk = blockIdx.x, b = blockIdx.y;
    int tid = threadIdx.x;
    int t0 = blk*TS4;
    __shared__ float  sv[C_][SVLEN];
    __shared__ float  swin[NFFT_];
    __shared__ float2 sG[TS4][C_][9][20];   // pre-twiddled G'[m][r]
    __shared__ float  sMean[4];
    __shared__ float  sInv;

    // finalize stats (warp 0)
    if(tid < 32){
        float4 s  = g_ssum[b*32+tid];
        float4 mx = g_smax[b*32+tid];
        float4 mn = g_smin[b*32+tid];
        for(int o = 16; o; o >>= 1){
            s.x += __shfl_xor_sync(~0u, s.x, o); s.y += __shfl_xor_sync(~0u, s.y, o);
            s.z += __shfl_xor_sync(~0u, s.z, o); s.w += __shfl_xor_sync(~0u, s.w, o);
            mx.x = fmaxf(mx.x, __shfl_xor_sync(~0u, mx.x, o)); mx.y = fmaxf(mx.y, __shfl_xor_sync(~0u, mx.y, o));
            mx.z = fmaxf(mx.z, __shfl_xor_sync(~0u, mx.z, o)); mx.w = fmaxf(mx.w, __shfl_xor_sync(~0u, mx.w, o));
            mn.x = fminf(mn.x, __shfl_xor_sync(~0u, mn.x, o)); mn.y = fminf(mn.y, __shfl_xor_sync(~0u, mn.y, o));
            mn.z = fminf(mn.z, __shfl_xor_sync(~0u, mn.z, o)); mn.w = fminf(mn.w, __shfl_xor_sync(~0u, mn.w, o));
        }
        if(tid == 0){
            float m0 = s.x/(float)L_, m1 = s.y/(float)L_, m2 = s.z/(float)L_, m3 = s.w/(float)L_;
            float a = fmaxf(fmaxf(mx.x-m0, m0-mn.x), fmaxf(mx.y-m1, m1-mn.y));
            a = fmaxf(a, fmaxf(fmaxf(mx.z-m2, m2-mn.z), fmaxf(mx.w-m3, m3-mn.w)));
            sMean[0]=m0; sMean[1]=m1; sMean[2]=m2; sMean[3]=m3; sInv = 1.0f/a;
        }
    }
    for(int i = tid; i < NFFT_; i += 256) swin[i] = win[i];
    __syncthreads();

    // load normalized sample strip (reflect pad)
    {
        float m0 = sMean[0], m1 = sMean[1], m2 = sMean[2], m3 = sMean[3], inv = sInv;
        for(int i = tid; i < SVLEN; i += 256){
            int l = t0*HOP_ + i - (NFFT_/2);
            if(l < 0) l = -l;
            else if(l >= L_) l = 2*L_ - 2 - l;
            float4 v = *(const float4*)(x + ((size_t)b*L_ + l)*C_);
            sv[0][i] = (v.x-m0)*inv; sv[1][i] = (v.y-m1)*inv;
            sv[2][i] = (v.z-m2)*inv; sv[3][i] = (v.w-m3)*inv;
        }
    }
    __syncthreads();

    // ---- stage 1: per (f,c,r): real DFT-16 over q (radix 4x4) + pre-twiddle W320^{-mr} ----
    for(int task = tid; task < TS4*C_*20; task += 256){
        int r = task % 20;
        int c = (task/20) & 3;
        int f = task/80;
        int base = f*HOP_ + r;
        // windowed gather
        float v[16];
        #pragma unroll
        for(int q = 0; q < 16; q++) v[q] = sv[c][base + 20*q] * swin[20*q + r];
        // inner DFT-4 over qa (real inputs, W4^{-j})
        float2 Bq[4][4];
        #pragma unroll
        for(int qb = 0; qb < 4; qb++){
            float v0=v[qb], v1=v[4+qb], v2=v[8+qb], v3=v[12+qb];
            float s0=v0+v2, d0=v0-v2, s1=v1+v3, d1=v1-v3;
            Bq[qb][0] = make_float2(s0+s1, 0.f);
            Bq[qb][2] = make_float2(s0-s1, 0.f);
            Bq[qb][1] = make_float2(d0, -d1);
            Bq[qb][3] = make_float2(d0,  d1);
        }
        // combine with W16^{-qb m} (immediates), then multiply by W320^{-mr}
        float sn, cs; sincospif(-(float)r/160.0f, &sn, &cs);
        float2 step = make_float2(cs, sn), w = make_float2(1.f, 0.f);
        #pragma unroll
        for(int m = 0; m < 9; m++){
            float2 acc = Bq[0][m&3];
            #pragma unroll
            for(int qb = 1; qb < 4; qb++){
                int j = (qb*m) & 15;
                float2 y = Bq[qb][m&3];
                acc.x += y.x*C16[j] + y.y*S16[j];
                acc.y += y.y*C16[j] - y.x*S16[j];
            }
            sG[f][c][m][r] = cmul(acc, w);
            w = cmul(w, step);
        }
    }
    __syncthreads();

    // ---- stage 2: per (f,c,m): constant DFT-20 over r -> bins k = 16a+m ----
    for(int task = tid; task < TS4*C_*16; task += 256){
        int m = task & 15;
        int c = (task >> 4) & 3;
        int f = task >> 6;
        int t = t0 + f;
        if(t >= T_) continue;
        float2 y[20];
        if(m <= 8){
            #pragma unroll
            for(int r = 0; r < 20; r++) y[r] = sG[f][c][m][r];
        } else {
            int mm = 16 - m;
            #pragma unroll
            for(int r = 0; r < 20; r++){
                float2 g = sG[f][c][mm][r];
                float gr = g.x, gi = -g.y;          // conj(G')
                y[r].x = gr*C20[r] + gi*S20[r];     // * W20^{-r}
                y[r].y = gi*C20[r] - gr*S20[r];
            }
        }
        // DFT-20 over r (radix 4x5, negative exponent): r = 5r1 + r2
        float2 D[5][4];
        #pragma unroll
        for(int r2 = 0; r2 < 5; r2++){
            float2 y0=y[r2], y1=y[5+r2], y2=y[10+r2], y3=y[15+r2];
            float2 s0=cadd(y0,y2), d0=csub(y0,y2), s1=cadd(y1,y3), d1=csub(y1,y3);
            D[r2][0] = cadd(s0,s1);
            D[r2][2] = csub(s0,s1);
            D[r2][1] = make_float2(d0.x + d1.y, d0.y - d1.x);   // d0 - i*d1
            D[r2][3] = make_float2(d0.x - d1.y, d0.y + d1.x);   // d0 + i*d1
        }
        int amax = (m == 0) ? 10 : 9;
        #pragma unroll
        for(int a = 0; a <= 10; a++){
            if(a > amax) break;
            float2 acc = D[0][a&3];
            #pragma unroll
            for(int r2 = 1; r2 < 5; r2++){
                int j = (a*r2) % 20;
                float2 dd = D[r2][a&3];
                acc.x += dd.x*C20[j] + dd.y*S20[j];
                acc.y += dd.y*C20[j] - dd.x*S20[j];
            }
            int k = 16*a + m;
            g_X[(((size_t)b*F_ + k)*T_ + t)*C_ + c] = acc;
        }
    }
}

// ---------------- MVDR beam: t-tiled in shared, LDL^H solve ----------------
struct LDLf { float iD0,iD1,iD2,iD3; float2 L10,L20,L30,L21,L31,L32; };

__device__ __forceinline__ float2 mvdr_beam(const LDLf& f,
    float2 h0, float2 h1, float2 h2, float2 h3,
    float2 X0, float2 X1, float2 X2, float2 X3)
{
    float2 z0 = h0;
    float2 z1 = csub(h1, cmul(f.L10, z0));
    float2 z2 = csub(csub(h2, cmul(f.L20, z0)), cmul(f.L21, z1));
    float2 z3 = csub(csub(csub(h3, cmul(f.L30, z0)), cmul(f.L31, z1)), cmul(f.L32, z2));
    float2 u0 = cscale(f.iD0, z0), u1 = cscale(f.iD1, z1);
    float2 u2 = cscale(f.iD2, z2), u3 = cscale(f.iD3, z3);
    float2 y3 = u3;
    float2 y2 = csub(u2, ccmul(f.L32, y3));
    float2 y1 = csub(csub(u1, ccmul(f.L21, y2)), ccmul(f.L31, y3));
    float2 y0 = csub(csub(csub(u0, ccmul(f.L10, y1)), ccmul(f.L20, y2)), ccmul(f.L30, y3));
    float2 den = cadd(cadd(ccmul(h0,y0), ccmul(h1,y1)), cadd(ccmul(h2,y2), ccmul(h3,y3)));
    float2 s   = cadd(cadd(ccmul(y0,X0), ccmul(y1,X1)), cadd(ccmul(y2,X2), ccmul(y3,X3)));
    float inv = 1.0f/(den.x*den.x + den.y*den.y);
    float2 sd = cmul(s, den);
    return make_float2(sd.x*inv, sd.y*inv);
}

__global__ void k_beam(){
    int tb = blockIdx.x, b = blockIdx.y, k = blockIdx.z;
    int tid = threadIdx.x;
    __shared__ float4 sX[(BT + KTAP - 1)*2];

    int ts = tb*BT - (KTAP-1);
    const float4* gx = (const float4*)g_X + ((size_t)(b*F_ + k))*T_*2;
    for(int i = tid; i < (BT + KTAP - 1)*2; i += BT){
        int tt = ts + (i >> 1);
        if(tt >= 0 && tt < T_) sX[i] = gx[(size_t)tt*2 + (i & 1)];
    }
    __syncthreads();

    int t = tb*BT + tid;
    if(t >= T_) return;

    int base = (tid + KTAP - 1)*2;
    float4 xa = sX[base], xb = sX[base+1];
    float2 X0 = make_float2(xa.x,xa.y), X1 = make_float2(xa.z,xa.w);
    float2 X2 = make_float2(xb.x,xb.y), X3 = make_float2(xb.z,xb.w);

    float d0=0,d1=0,d2=0,d3=0;
    float2 m10={0,0}, m20={0,0}, m21={0,0}, m30={0,0}, m31={0,0}, m32={0,0};

    #pragma unroll
    for(int j = 0; j < KTAP; j++){
        int s = t - j;
        if(s < 0) break;
        float cf = (s == 0) ? c_p05[t] : c_c95[j];
        float2 y0,y1,y2,y3;
        if(j == 0){ y0=X0; y1=X1; y2=X2; y3=X3; }
        else{
            float4 a = sX[base - 2*j], bb = sX[base - 2*j + 1];
            y0 = make_float2(a.x,a.y); y1 = make_float2(a.z,a.w);
            y2 = make_float2(bb.x,bb.y); y3 = make_float2(bb.z,bb.w);
        }
        float2 u0 = cscale(cf,y0), u1 = cscale(cf,y1), u2 = cscale(cf,y2), u3 = cscale(cf,y3);
        d0 += u0.x*y0.x + u0.y*y0.y;
        d1 += u1.x*y1.x + u1.y*y1.y;
        d2 += u2.x*y2.x + u2.y*y2.y;
        d3 += u3.x*y3.x + u3.y*y3.y;
        m10 = cadd(m10, cmulc(u1,y0));
        m20 = cadd(m20, cmulc(u2,y0));
        m21 = cadd(m21, cmulc(u2,y1));
        m30 = cadd(m30, cmulc(u3,y0));
        m31 = cadd(m31, cmulc(u3,y1));
        m32 = cadd(m32, cmulc(u3,y2));
    }

    float tr4 = 0.25f*(d0+d1+d2+d3);
    float a0 = d0+tr4, a1 = d1+tr4, a2 = d2+tr4, a3 = d3+tr4;

    LDLf f;
    f.iD0 = 1.0f/a0;
    f.L10 = cscale(f.iD0, m10); f.L20 = cscale(f.iD0, m20); f.L30 = cscale(f.iD0, m30);
    float D1 = a1 - (m10.x*f.L10.x + m10.y*f.L10.y);
    f.iD1 = 1.0f/D1;
    float2 t21 = csub(m21, cmulc(m20, f.L10));
    f.L21 = cscale(f.iD1, t21);
    float2 t31 = csub(m31, cmulc(m30, f.L10));
    f.L31 = cscale(f.iD1, t31);
    float D2 = a2 - (m20.x*f.L20.x + m20.y*f.L20.y) - (t21.x*f.L21.x + t21.y*f.L21.y);
    f.iD2 = 1.0f/D2;
    float2 t32 = csub(csub(m32, cmulc(m30, f.L20)), cmulc(t31, f.L21));
    f.L32 = cscale(f.iD2, t32);
    float D3 = a3 - (m30.x*f.L30.x + m30.y*f.L30.y)
                  - (t31.x*f.L31.x + t31.y*f.L31.y)
                  - (t32.x*f.L32.x + t32.y*f.L32.y);
    f.iD3 = 1.0f/D3;

    const float phi = (float)(6.283185307179586 * 50.0 * 0.027 * 0.6427876096865393 / 340.0);
    float ang = phi * (float)k;
    float s1, c1; sincosf(ang, &s1, &c1);
    float c2 = c1*c1 - s1*s1, s2 = 2.f*c1*s1;
    float c3 = c2*c1 - s2*s1, s3 = s2*c1 + c2*s1;

    float2 one = make_float2(1.f, 0.f);
    float2 o1 = mvdr_beam(f, one, make_float2(c1,-s1), make_float2(c2,-s2), make_float2(c3,-s3),
                          X0, X1, X2, X3);
    float2 o2 = mvdr_beam(f, one, make_float2(c1, s1), make_float2(c2, s2), make_float2(c3, s3),
                          X0, X1, X2, X3);

    g_Y[((size_t)(0*B_+b)*F_ + k)*T_ + t] = o1;
    g_Y[((size_t)(1*B_+b)*F_ + k)*T_ + t] = o2;
}

// ---------------- ISTFT + OLA fused ----------------
__global__ void k_istft(float* __restrict__ out){
    const float C20[20] = { 1.f, 0.9510565163f, 0.8090169944f, 0.5877852523f, 0.3090169944f,
                            0.f,-0.3090169944f,-0.5877852523f,-0.8090169944f,-0.9510565163f,
                           -1.f,-0.9510565163f,-0.8090169944f,-0.5877852523f,-0.3090169944f,
                            0.f, 0.3090169944f, 0.5877852523f, 0.8090169944f, 0.9510565163f };
    const float S20[20] = { 0.f, 0.3090169944f, 0.5877852523f, 0.8090169944f, 0.9510565163f,
                            1.f, 0.9510565163f, 0.8090169944f, 0.5877852523f, 0.3090169944f,
                            0.f,-0.3090169944f,-0.5877852523f,-0.8090169944f,-0.9510565163f,
                           -1.f,-0.9510565163f,-0.8090169944f,-0.5877852523f,-0.3090169944f };
    const float C16[16] = { 1.f, 0.9238795325f, 0.7071067812f, 0.3826834324f, 0.f,
                           -0.3826834324f,-0.7071067812f,-0.9238795325f,-1.f,-0.9238795325f,
                           -0.7071067812f,-0.3826834324f, 0.f, 0.3826834324f, 0.7071067812f, 0.9238795325f };
    const float S16[16] = { 0.f, 0.3826834324f, 0.7071067812f, 0.9238795325f, 1.f,
                            0.9238795325f, 0.7071067812f, 0.3826834324f, 0.f,-0.3826834324f,
                           -0.7071067812f,-0.9238795325f,-1.f,-0.9238795325f,-0.7071067812f,-0.3826834324f };

    int blk = blockIdx.x, b = blockIdx.y, beam = blockIdx.z;
    int tid = threadIdx.x;
    int t0  = blk*NQ;
    __shared__ float2 sH[9][20][TF+1];
    __shared__ float  sFr[TF][322];

    size_t ybase = (size_t)(beam*B_+b)*F_*T_;

    {
        int k1 = tid >> 4;
        int f  = tid & 15;
        if(k1 < 9){
            int t = t0 + f;
            float2 z[20];
            if(t < T_){
                #pragma unroll
                for(int k2 = 0; k2 < 20; k2++){
                    int kk = 16*k2 + k1;
                    float2 v;
                    if(kk <= 160){
                        v = g_Y[ybase + (size_t)kk*T_ + t];
                        if(k1 == 0 && (k2 == 0 || k2 == 10)) v.y = 0.f;
                    } else {
                        v = g_Y[ybase + (size_t)(320-kk)*T_ + t];
                        v.y = -v.y;
                    }
                    z[k2] = v;
                }
            } else {
                #pragma unroll
                for(int k2 = 0; k2 < 20; k2++) z[k2] = make_float2(0.f,0.f);
            }
            float2 Y[5][4];
            #pragma unroll
            for(int bq = 0; bq < 5; bq++){
                float2 z0=z[bq], z1=z[bq+5], z2=z[bq+10], z3=z[bq+15];
                float2 s0=cadd(z0,z2), s1=csub(z0,z2), s2=cadd(z1,z3), s3=csub(z1,z3);
                Y[bq][0] = cadd(s0,s2);
                Y[bq][2] = csub(s0,s2);
                Y[bq][1] = make_float2(s1.x - s3.y, s1.y + s3.x);
                Y[bq][3] = make_float2(s1.x + s3.y, s1.y - s3.x);
            }
            float sc = (k1==0 || k1==8) ? 1.f : 2.f;
            #pragma unroll
            for(int p = 0; p < 20; p++){
                float2 acc = Y[0][p&3];
                #pragma unroll
                for(int bq = 1; bq < 5; bq++){
                    float cw = C20[(bq*p)%20], sw = S20[(bq*p)%20];
                    float2 y = Y[bq][p&3];
                    acc.x += cw*y.x - sw*y.y;
                    acc.y += cw*y.y + sw*y.x;
                }
                sH[k1][p][f] = make_float2(sc*acc.x, sc*acc.y);
            }
        }
    }
    __syncthreads();

    for(int task = tid; task < 20*TF; task += 288){
        int pm = task >> 4;
        int f  = task & 15;
        float sn, cs; sincospif((float)pm/160.0f, &sn, &cs);
        float2 wst = make_float2(cs, sn), w = make_float2(1.f, 0.f);
        float2 a[9];
        a[0] = sH[0][pm][f];
        #pragma unroll
        for(int k1 = 1; k1 < 9; k1++){
            w = cmul(w, wst);
            a[k1] = cmul(sH[k1][pm][f], w);
        }
        #pragma unroll
        for(int u = 0; u < 16; u++){
            float acc = a[0].x;
            #pragma unroll
            for(int k1 = 1; k1 < 9; k1++){
                int j = (k1*u) & 15;
                acc += a[k1].x*C16[j] - a[k1].y*S16[j];
            }
            sFr[f][20*u + pm] = acc * (1.0f/640.0f);
        }
    }
    __syncthreads();

    int qmax = min(t0 + NQ, T_ - 1);
    int nq = qmax - t0;
    float* po = out + (size_t)(beam*B_+b)*L_;
    for(int task = tid; task < nq*80; task += 288){
        int qi = task / 80;
        int rr = (task - qi*80)*2;
        int q  = t0 + 1 + qi;
        int fq = qi + 1;
        float v0 = sFr[fq][rr]   + sFr[fq-1][160+rr];
        float v1 = sFr[fq][rr+1] + sFr[fq-1][161+rr];
        *(float2*)(po + (size_t)(q-1)*160 + rr) = make_float2(v0, v1);
    }
}

// ---------------- launch ----------------
extern "C" void kernel_launch(void* const* d_in, const int* in_sizes, int n_in,
                              void* d_out, int out_size){
    const float* x   = (const float*)d_in[0];
    const float* win = (const float*)d_in[1];
    float* out = (float*)d_out;

    k_stats<<<dim3(32, B_), 256>>>(x);
    k_stft <<<dim3((T_+TS4-1)/TS4, B_), 256>>>(x, win);
    k_beam <<<dim3((T_+BT-1)/BT, B_, F_), BT>>>();
    k_istft<<<dim3((T_-1+NQ-1)/NQ, B_, 2), 288>>>(out);
}

// round 7
// speedup vs baseline: 6.1514x; 1.0748x over previous
#include <cuda_runtime.h>
#include <math.h>

#define B_    8
#define L_    160000
#define C_    4
#define NFFT_ 320
#define HOP_  160
#define T_    1001
#define F_    161
#define KTAP  6
#define TSEQ  8          // beam: consecutive t per thread (serial IIR chain)
#define NQ    15         // istft: output q-segments per block
#define TF    16         // istft: frames per block (NQ+1)
#define TS4   4          // stft: frames per block
#define SVLEN (160*TS4 + 160)   // 800

// ---------------- scratch ----------------
__device__ float2 g_X [(size_t)B_*F_*T_*C_];    // STFT  [b][k][t][c]
__device__ float2 g_Y [(size_t)2*B_*F_*T_];     // beams [beam][b][k][t]
__device__ float4 g_ssum[B_*32];
__device__ float4 g_smax[B_*32];
__device__ float4 g_smin[B_*32];

__constant__ float c_c95[10] = {0.95f, 0.0475f, 2.375e-3f, 1.1875e-4f, 5.9375e-6f,
                                2.96875e-7f, 1.484375e-8f, 7.421875e-10f,
                                3.7109375e-11f, 1.85546875e-12f};
__constant__ float c_p05[10] = {1.0f, 0.05f, 2.5e-3f, 1.25e-4f, 6.25e-6f,
                                3.125e-7f, 1.5625e-8f, 7.8125e-10f,
                                3.90625e-11f, 1.953125e-12f};

// ---------------- complex helpers ----------------
__device__ __forceinline__ float2 cadd(float2 a, float2 b){ return make_float2(a.x+b.x, a.y+b.y); }
__device__ __forceinline__ float2 csub(float2 a, float2 b){ return make_float2(a.x-b.x, a.y-b.y); }
__device__ __forceinline__ float2 cmul(float2 a, float2 b){ return make_float2(a.x*b.x-a.y*b.y, a.x*b.y+a.y*b.x); }
__device__ __forceinline__ float2 ccmul(float2 a, float2 b){ return make_float2(a.x*b.x+a.y*b.y, a.x*b.y-a.y*b.x); } // conj(a)*b
__device__ __forceinline__ float2 cmulc(float2 a, float2 b){ return make_float2(a.x*b.x+a.y*b.y, a.y*b.x-a.x*b.y); } // a*conj(b)
__device__ __forceinline__ float2 cscale(float s, float2 a){ return make_float2(s*a.x, s*a.y); }

// ---------------- single-pass stats ----------------
__global__ void k_stats(const float* __restrict__ x){
    int b = blockIdx.y, ch = blockIdx.x;
    int l0 = ch*5000;
    float4 s  = make_float4(0.f,0.f,0.f,0.f);
    float4 mx = make_float4(-1e30f,-1e30f,-1e30f,-1e30f);
    float4 mn = make_float4( 1e30f, 1e30f, 1e30f, 1e30f);
    for(int l = l0 + threadIdx.x; l < l0+5000; l += 256){
        float4 v = *(const float4*)(x + ((size_t)b*L_ + l)*C_);
        s.x += v.x; s.y += v.y; s.z += v.z; s.w += v.w;
        mx.x = fmaxf(mx.x,v.x); mx.y = fmaxf(mx.y,v.y); mx.z = fmaxf(mx.z,v.z); mx.w = fmaxf(mx.w,v.w);
        mn.x = fminf(mn.x,v.x); mn.y = fminf(mn.y,v.y); mn.z = fminf(mn.z,v.z); mn.w = fminf(mn.w,v.w);
    }
    __shared__ float4 rs[256], rx[256], rn[256];
    rs[threadIdx.x]=s; rx[threadIdx.x]=mx; rn[threadIdx.x]=mn; __syncthreads();
    for(int st = 128; st > 0; st >>= 1){
        if(threadIdx.x < st){
            float4 o = rs[threadIdx.x+st];
            rs[threadIdx.x].x += o.x; rs[threadIdx.x].y += o.y; rs[threadIdx.x].z += o.z; rs[threadIdx.x].w += o.w;
            float4 a = rx[threadIdx.x+st];
            rx[threadIdx.x].x = fmaxf(rx[threadIdx.x].x,a.x); rx[threadIdx.x].y = fmaxf(rx[threadIdx.x].y,a.y);
            rx[threadIdx.x].z = fmaxf(rx[threadIdx.x].z,a.z); rx[threadIdx.x].w = fmaxf(rx[threadIdx.x].w,a.w);
            float4 c = rn[threadIdx.x+st];
            rn[threadIdx.x].x = fminf(rn[threadIdx.x].x,c.x); rn[threadIdx.x].y = fminf(rn[threadIdx.x].y,c.y);
            rn[threadIdx.x].z = fminf(rn[threadIdx.x].z,c.z); rn[threadIdx.x].w = fminf(rn[threadIdx.x].w,c.w);
        }
        __syncthreads();
    }
    if(threadIdx.x == 0){
        g_ssum[b*32+ch] = rs[0]; g_smax[b*32+ch] = rx[0]; g_smin[b*32+ch] = rn[0];
    }
}

// ---------------- STFT: 4 frames/block, register radix DFT-16 + constant DFT-20 ----------------
__global__ void k_stft(const float* __restrict__ x, const float* __restrict__ win){
    const float C16[16] = { 1.f, 0.9238795325f, 0.7071067812f, 0.3826834324f, 0.f,
                           -0.3826834324f,-0.7071067812f,-0.9238795325f,-1.f,-0.9238795325f,
                           -0.7071067812f,-0.3826834324f, 0.f, 0.3826834324f, 0.7071067812f, 0.9238795325f };
    const float S16[16] = { 0.f, 0.3826834324f, 0.7071067812f, 0.9238795325f, 1.f,
                            0.9238795325f, 0.7071067812f, 0.3826834324f, 0.f,-0.3826834324f,
                           -0.7071067812f,-0.9238795325f,-1.f,-0.9238795325f,-0.7071067812f,-0.3826834324f };
    const float C20[20] = { 1.f, 0.9510565163f, 0.8090169944f, 0.5877852523f, 0.3090169944f,
                            0.f,-0.3090169944f,-0.5877852523f,-0.8090169944f,-0.9510565163f,
                           -1.f,-0.9510565163f,-0.8090169944f,-0.5877852523f,-0.3090169944f,
                            0.f, 0.3090169944f, 0.5877852523f, 0.8090169944f, 0.9510565163f };
    const float S20[20] = { 0.f, 0.3090169944f, 0.5877852523f, 0.8090169944f, 0.9510565163f,
                            1.f, 0.9510565163f, 0.8090169944f, 0.5877852523f, 0.3090169944f,
                            0.f,-0.3090169944f,-0.5877852523f,-0.8090169944f,-0.9510565163f,
                           -1.f,-0.9510565163f,-0.8090169944f,-0.5877852523f,-0.3090169944f };

    int blk = blockIdx.x, b = blockIdx.y;
    int tid = threadIdx.x;
    int t0 = blk*TS4;
    __shared__ float  sv[C_][SVLEN];
    __shared__ float  swin[NFFT_];
    __shared__ float2 sG[TS4][C_][9][20];
    __shared__ float  sMean[4];
    __shared__ float  sInv;

    if(tid < 32){
        float4 s  = g_ssum[b*32+tid];
        float4 mx = g_smax[b*32+tid];
        float4 mn = g_smin[b*32+tid];
        for(int o = 16; o; o >>= 1){
            s.x += __shfl_xor_sync(~0u, s.x, o); s.y += __shfl_xor_sync(~0u, s.y, o);
            s.z += __shfl_xor_sync(~0u, s.z, o); s.w += __shfl_xor_sync(~0u, s.w, o);
            mx.x = fmaxf(mx.x, __shfl_xor_sync(~0u, mx.x, o)); mx.y = fmaxf(mx.y, __shfl_xor_sync(~0u, mx.y, o));
            mx.z = fmaxf(mx.z, __shfl_xor_sync(~0u, mx.z, o)); mx.w = fmaxf(mx.w, __shfl_xor_sync(~0u, mx.w, o));
            mn.x = fminf(mn.x, __shfl_xor_sync(~0u, mn.x, o)); mn.y = fminf(mn.y, __shfl_xor_sync(~0u, mn.y, o));
            mn.z = fminf(mn.z, __shfl_xor_sync(~0u, mn.z, o)); mn.w = fminf(mn.w, __shfl_xor_sync(~0u, mn.w, o));
        }
        if(tid == 0){
            float m0 = s.x/(float)L_, m1 = s.y/(float)L_, m2 = s.z/(float)L_, m3 = s.w/(float)L_;
            float a = fmaxf(fmaxf(mx.x-m0, m0-mn.x), fmaxf(mx.y-m1, m1-mn.y));
            a = fmaxf(a, fmaxf(fmaxf(mx.z-m2, m2-mn.z), fmaxf(mx.w-m3, m3-mn.w)));
            sMean[0]=m0; sMean[1]=m1; sMean[2]=m2; sMean[3]=m3; sInv = 1.0f/a;
        }
    }
    for(int i = tid; i < NFFT_; i += 256) swin[i] = win[i];
    __syncthreads();

    {
        float m0 = sMean[0], m1 = sMean[1], m2 = sMean[2], m3 = sMean[3], inv = sInv;
        for(int i = tid; i < SVLEN; i += 256){
            int l = t0*HOP_ + i - (NFFT_/2);
            if(l < 0) l = -l;
            else if(l >= L_) l = 2*L_ - 2 - l;
            float4 v = *(const float4*)(x + ((size_t)b*L_ + l)*C_);
            sv[0][i] = (v.x-m0)*inv; sv[1][i] = (v.y-m1)*inv;
            sv[2][i] = (v.z-m2)*inv; sv[3][i] = (v.w-m3)*inv;
        }
    }
    __syncthreads();

    for(int task = tid; task < TS4*C_*20; task += 256){
        int r = task % 20;
        int c = (task/20) & 3;
        int f = task/80;
        int base = f*HOP_ + r;
        float v[16];
        #pragma unroll
        for(int q = 0; q < 16; q++) v[q] = sv[c][base + 20*q] * swin[20*q + r];
        float2 Bq[4][4];
        #pragma unroll
        for(int qb = 0; qb < 4; qb++){
            float v0=v[qb], v1=v[4+qb], v2=v[8+qb], v3=v[12+qb];
            float s0=v0+v2, d0=v0-v2, s1=v1+v3, d1=v1-v3;
            Bq[qb][0] = make_float2(s0+s1, 0.f);
            Bq[qb][2] = make_float2(s0-s1, 0.f);
            Bq[qb][1] = make_float2(d0, -d1);
            Bq[qb][3] = make_float2(d0,  d1);
        }
        float sn, cs; sincospif(-(float)r/160.0f, &sn, &cs);
        float2 step = make_float2(cs, sn), w = make_float2(1.f, 0.f);
        #pragma unroll
        for(int m = 0; m < 9; m++){
            float2 acc = Bq[0][m&3];
            #pragma unroll
            for(int qb = 1; qb < 4; qb++){
                int j = (qb*m) & 15;
                float2 y = Bq[qb][m&3];
                acc.x += y.x*C16[j] + y.y*S16[j];
                acc.y += y.y*C16[j] - y.x*S16[j];
            }
            sG[f][c][m][r] = cmul(acc, w);
            w = cmul(w, step);
        }
    }
    __syncthreads();

    for(int task = tid; task < TS4*C_*16; task += 256){
        int m = task & 15;
        int c = (task >> 4) & 3;
        int f = task >> 6;
        int t = t0 + f;
        if(t >= T_) continue;
        float2 y[20];
        if(m <= 8){
            #pragma unroll
            for(int r = 0; r < 20; r++) y[r] = sG[f][c][m][r];
        } else {
            int mm = 16 - m;
            #pragma unroll
            for(int r = 0; r < 20; r++){
                float2 g = sG[f][c][mm][r];
                float gr = g.x, gi = -g.y;
                y[r].x = gr*C20[r] + gi*S20[r];
                y[r].y = gi*C20[r] - gr*S20[r];
            }
        }
        float2 D[5][4];
        #pragma unroll
        for(int r2 = 0; r2 < 5; r2++){
            float2 y0=y[r2], y1=y[5+r2], y2=y[10+r2], y3=y[15+r2];
            float2 s0=cadd(y0,y2), d0=csub(y0,y2), s1=cadd(y1,y3), d1=csub(y1,y3);
            D[r2][0] = cadd(s0,s1);
            D[r2][2] = csub(s0,s1);
            D[r2][1] = make_float2(d0.x + d1.y, d0.y - d1.x);
            D[r2][3] = make_float2(d0.x - d1.y, d0.y + d1.x);
        }
        int amax = (m == 0) ? 10 : 9;
        #pragma unroll
        for(int a = 0; a <= 10; a++){
            if(a > amax) break;
            float2 acc = D[0][a&3];
            #pragma unroll
            for(int r2 = 1; r2 < 5; r2++){
                int j = (a*r2) % 20;
                float2 dd = D[r2][a&3];
                acc.x += dd.x*C20[j] + dd.y*S20[j];
                acc.y += dd.y*C20[j] - dd.x*S20[j];
            }
            int k = 16*a + m;
            g_X[(((size_t)b*F_ + k)*T_ + t)*C_ + c] = acc;
        }
    }
}

// ---------------- MVDR beam: serial IIR chain, LDL^H solve, real denominator ----------------
struct LDLf { float iD0,iD1,iD2,iD3; float2 L10,L20,L30,L21,L31,L32; };

__device__ __forceinline__ float2 mvdr_beam2(const LDLf& f,
    float2 h1, float2 h2, float2 h3,          // h0 = 1
    float2 X0, float2 X1, float2 X2, float2 X3)
{
    // forward: L z = h (unit lower, z0 = 1)
    float2 z1 = csub(h1, f.L10);
    float2 z2 = csub(csub(h2, f.L20), cmul(f.L21, z1));
    float2 z3 = csub(csub(csub(h3, f.L30), cmul(f.L31, z1)), cmul(f.L32, z2));
    // backward: L^H y = D^{-1} z
    float2 y3 = cscale(f.iD3, z3);
    float2 y2 = csub(cscale(f.iD2, z2), ccmul(f.L32, y3));
    float2 y1 = csub(csub(cscale(f.iD1, z1), ccmul(f.L21, y2)), ccmul(f.L31, y3));
    float2 y0 = csub(csub(csub(make_float2(f.iD0, 0.f), ccmul(f.L10, y1)), ccmul(f.L20, y2)), ccmul(f.L30, y3));
    // den = h^H y  (exactly real for Hermitian PD A)
    float den = y0.x + (h1.x*y1.x + h1.y*y1.y) + (h2.x*y2.x + h2.y*y2.y) + (h3.x*y3.x + h3.y*y3.y);
    float2 s  = cadd(cadd(ccmul(y0,X0), ccmul(y1,X1)), cadd(ccmul(y2,X2), ccmul(y3,X3)));
    float inv = 1.0f/den;
    return make_float2(s.x*inv, s.y*inv);
}

__global__ void k_beam(){
    int k = blockIdx.x, b = blockIdx.y;
    int tid = threadIdx.x;
    int t0 = tid*TSEQ;
    if(t0 >= T_) return;

    const float4* gx = (const float4*)g_X + ((size_t)(b*F_ + k))*T_*2;

    // steering phases (h(+40) = e^{+i c phi}, h(-40) = conj)
    const float phi = (float)(6.283185307179586 * 50.0 * 0.027 * 0.6427876096865393 / 340.0);
    float ang = phi * (float)k;
    float s1, c1; sincosf(ang, &s1, &c1);
    float c2 = c1*c1 - s1*s1, s2 = 2.f*c1*s1;
    float c3 = c2*c1 - s2*s1, s3 = s2*c1 + c2*s1;

    // covariance accumulators
    float d0=0,d1=0,d2=0,d3=0;
    float2 m10={0,0}, m20={0,0}, m21={0,0}, m30={0,0}, m31={0,0}, m32={0,0};

    // warm-up: truncated R_{t0-1}
    int tw = t0 - 1;
    if(tw >= 0){
        #pragma unroll
        for(int j = 0; j < KTAP; j++){
            int s = tw - j;
            if(s < 0) break;
            float cf = (s == 0) ? c_p05[tw] : c_c95[j];
            float4 a = gx[(size_t)s*2], bb = gx[(size_t)s*2+1];
            float2 y0 = make_float2(a.x,a.y), y1 = make_float2(a.z,a.w);
            float2 y2 = make_float2(bb.x,bb.y), y3 = make_float2(bb.z,bb.w);
            d0 += cf*(y0.x*y0.x + y0.y*y0.y);
            d1 += cf*(y1.x*y1.x + y1.y*y1.y);
            d2 += cf*(y2.x*y2.x + y2.y*y2.y);
            d3 += cf*(y3.x*y3.x + y3.y*y3.y);
            m10 = cadd(m10, cscale(cf, cmulc(y1,y0)));
            m20 = cadd(m20, cscale(cf, cmulc(y2,y0)));
            m21 = cadd(m21, cscale(cf, cmulc(y2,y1)));
            m30 = cadd(m30, cscale(cf, cmulc(y3,y0)));
            m31 = cadd(m31, cscale(cf, cmulc(y3,y1)));
            m32 = cadd(m32, cscale(cf, cmulc(y3,y2)));
        }
    }

    size_t yb0 = ((size_t)(0*B_+b)*F_ + k)*T_;
    size_t yb1 = ((size_t)(1*B_+b)*F_ + k)*T_;

    #pragma unroll
    for(int i = 0; i < TSEQ; i++){
        int t = t0 + i;
        if(t >= T_) break;
        float4 xa = gx[(size_t)t*2], xb = gx[(size_t)t*2+1];
        float2 X0 = make_float2(xa.x,xa.y), X1 = make_float2(xa.z,xa.w);
        float2 X2 = make_float2(xb.x,xb.y), X3 = make_float2(xb.z,xb.w);

        if(t == 0){
            d0 = X0.x*X0.x + X0.y*X0.y;
            d1 = X1.x*X1.x + X1.y*X1.y;
            d2 = X2.x*X2.x + X2.y*X2.y;
            d3 = X3.x*X3.x + X3.y*X3.y;
            m10 = cmulc(X1,X0); m20 = cmulc(X2,X0); m21 = cmulc(X2,X1);
            m30 = cmulc(X3,X0); m31 = cmulc(X3,X1); m32 = cmulc(X3,X2);
        } else {
            d0 = 0.05f*d0 + 0.95f*(X0.x*X0.x + X0.y*X0.y);
            d1 = 0.05f*d1 + 0.95f*(X1.x*X1.x + X1.y*X1.y);
            d2 = 0.05f*d2 + 0.95f*(X2.x*X2.x + X2.y*X2.y);
            d3 = 0.05f*d3 + 0.95f*(X3.x*X3.x + X3.y*X3.y);
            m10 = cadd(cscale(0.05f,m10), cscale(0.95f, cmulc(X1,X0)));
            m20 = cadd(cscale(0.05f,m20), cscale(0.95f, cmulc(X2,X0)));
            m21 = cadd(cscale(0.05f,m21), cscale(0.95f, cmulc(X2,X1)));
            m30 = cadd(cscale(0.05f,m30), cscale(0.95f, cmulc(X3,X0)));
            m31 = cadd(cscale(0.05f,m31), cscale(0.95f, cmulc(X3,X1)));
            m32 = cadd(cscale(0.05f,m32), cscale(0.95f, cmulc(X3,X2)));
        }

        // diagonal loading
        float tr4 = 0.25f*(d0+d1+d2+d3);
        float a0 = d0+tr4, a1 = d1+tr4, a2 = d2+tr4, a3 = d3+tr4;

        // LDL^H
        LDLf f;
        f.iD0 = 1.0f/a0;
        f.L10 = cscale(f.iD0, m10); f.L20 = cscale(f.iD0, m20); f.L30 = cscale(f.iD0, m30);
        float D1 = a1 - (m10.x*f.L10.x + m10.y*f.L10.y);
        f.iD1 = 1.0f/D1;
        float2 t21 = csub(m21, cmulc(m20, f.L10));
        f.L21 = cscale(f.iD1, t21);
        float2 t31 = csub(m31, cmulc(m30, f.L10));
        f.L31 = cscale(f.iD1, t31);
        float D2 = a2 - (m20.x*f.L20.x + m20.y*f.L20.y) - (t21.x*f.L21.x + t21.y*f.L21.y);
        f.iD2 = 1.0f/D2;
        float2 t32 = csub(csub(m32, cmulc(m30, f.L20)), cmulc(t31, f.L21));
        f.L32 = cscale(f.iD2, t32);
        float D3 = a3 - (m30.x*f.L30.x + m30.y*f.L30.y)
                      - (t31.x*f.L31.x + t31.y*f.L31.y)
                      - (t32.x*f.L32.x + t32.y*f.L32.y);
        f.iD3 = 1.0f/D3;

        float2 o1 = mvdr_beam2(f, make_float2(c1,-s1), make_float2(c2,-s2), make_float2(c3,-s3),
                               X0, X1, X2, X3);
        float2 o2 = mvdr_beam2(f, make_float2(c1, s1), make_float2(c2, s2), make_float2(c3, s3),
                               X0, X1, X2, X3);
        g_Y[yb0 + t] = o1;
        g_Y[yb1 + t] = o2;
    }
}

// ---------------- ISTFT + OLA fused ----------------
__global__ void k_istft(float* __restrict__ out){
    const float C20[20] = { 1.f, 0.9510565163f, 0.8090169944f, 0.5877852523f, 0.3090169944f,
                            0.f,-0.3090169944f,-0.5877852523f,-0.8090169944f,-0.9510565163f,
                           -1.f,-0.9510565163f,-0.8090169944f,-0.5877852523f,-0.3090169944f,
                            0.f, 0.3090169944f, 0.5877852523f, 0.8090169944f, 0.9510565163f };
    const float S20[20] = { 0.f, 0.3090169944f, 0.5877852523f, 0.8090169944f, 0.9510565163f,
                            1.f, 0.9510565163f, 0.8090169944f, 0.5877852523f, 0.3090169944f,
                            0.f,-0.3090169944f,-0.5877852523f,-0.8090169944f,-0.9510565163f,
                           -1.f,-0.9510565163f,-0.8090169944f,-0.5877852523f,-0.3090169944f };
    const float C16[16] = { 1.f, 0.9238795325f, 0.7071067812f, 0.3826834324f, 0.f,
                           -0.3826834324f,-0.7071067812f,-0.9238795325f,-1.f,-0.9238795325f,
                           -0.7071067812f,-0.3826834324f, 0.f, 0.3826834324f, 0.7071067812f, 0.9238795325f };
    const float S16[16] = { 0.f, 0.3826834324f, 0.7071067812f, 0.9238795325f, 1.f,
                            0.9238795325f, 0.7071067812f, 0.3826834324f, 0.f,-0.3826834324f,
                           -0.7071067812f,-0.9238795325f,-1.f,-0.9238795325f,-0.7071067812f,-0.3826834324f };

    int blk = blockIdx.x, b = blockIdx.y, beam = blockIdx.z;
    int tid = threadIdx.x;
    int t0  = blk*NQ;
    __shared__ float2 sH[9][20][TF+1];
    __shared__ float  sFr[TF][322];

    size_t ybase = (size_t)(beam*B_+b)*F_*T_;

    {
        int k1 = tid >> 4;
        int f  = tid & 15;
        if(k1 < 9){
            int t = t0 + f;
            float2 z[20];
            if(t < T_){
                #pragma unroll
                for(int k2 = 0; k2 < 20; k2++){
                    int kk = 16*k2 + k1;
                    float2 v;
                    if(kk <= 160){
                        v = g_Y[ybase + (size_t)kk*T_ + t];
                        if(k1 == 0 && (k2 == 0 || k2 == 10)) v.y = 0.f;
                    } else {
                        v = g_Y[ybase + (size_t)(320-kk)*T_ + t];
                        v.y = -v.y;
                    }
                    z[k2] = v;
                }
            } else {
                #pragma unroll
                for(int k2 = 0; k2 < 20; k2++) z[k2] = make_float2(0.f,0.f);
            }
            float2 Y[5][4];
            #pragma unroll
            for(int bq = 0; bq < 5; bq++){
                float2 z0=z[bq], z1=z[bq+5], z2=z[bq+10], z3=z[bq+15];
                float2 s0=cadd(z0,z2), s1=csub(z0,z2), s2=cadd(z1,z3), s3=csub(z1,z3);
                Y[bq][0] = cadd(s0,s2);
                Y[bq][2] = csub(s0,s2);
                Y[bq][1] = make_float2(s1.x - s3.y, s1.y + s3.x);
                Y[bq][3] = make_float2(s1.x + s3.y, s1.y - s3.x);
            }
            float sc = (k1==0 || k1==8) ? 1.f : 2.f;
            #pragma unroll
            for(int p = 0; p < 20; p++){
                float2 acc = Y[0][p&3];
                #pragma unroll
                for(int bq = 1; bq < 5; bq++){
                    float cw = C20[(bq*p)%20], sw = S20[(bq*p)%20];
                    float2 y = Y[bq][p&3];
                    acc.x += cw*y.x - sw*y.y;
                    acc.y += cw*y.y + sw*y.x;
                }
                sH[k1][p][f] = make_float2(sc*acc.x, sc*acc.y);
            }
        }
    }
    __syncthreads();

    for(int task = tid; task < 20*TF; task += 288){
        int pm = task >> 4;
        int f  = task & 15;
        float sn, cs; sincospif((float)pm/160.0f, &sn, &cs);
        float2 wst = make_float2(cs, sn), w = make_float2(1.f, 0.f);
        float2 a[9];
        a[0] = sH[0][pm][f];
        #pragma unroll
        for(int k1 = 1; k1 < 9; k1++){
            w = cmul(w, wst);
            a[k1] = cmul(sH[k1][pm][f], w);
        }
        #pragma unroll
        for(int u = 0; u < 16; u++){
            float acc = a[0].x;
            #pragma unroll
            for(int k1 = 1; k1 < 9; k1++){
                int j = (k1*u) & 15;
                acc += a[k1].x*C16[j] - a[k1].y*S16[j];
            }
            sFr[f][20*u + pm] = acc * (1.0f/640.0f);
        }
    }
    __syncthreads();

    int qmax = min(t0 + NQ, T_ - 1);
    int nq = qmax - t0;
    float* po = out + (size_t)(beam*B_+b)*L_;
    for(int task = tid; task < nq*80; task += 288){
        int qi = task / 80;
        int rr = (task - qi*80)*2;
        int q  = t0 + 1 + qi;
        int fq = qi + 1;
        float v0 = sFr[fq][rr]   + sFr[fq-1][160+rr];
        float v1 = sFr[fq][rr+1] + sFr[fq-1][161+rr];
        *(float2*)(po + (size_t)(q-1)*160 + rr) = make_float2(v0, v1);
    }
}

// ---------------- launch ----------------
extern "C" void kernel_launch(void* const* d_in, const int* in_sizes, int n_in,
                              void* d_out, int out_size){
    const float* x   = (const float*)d_in[0];
    const float* win = (const float*)d_in[1];
    float* out = (float*)d_out;

    k_stats<<<dim3(32, B_), 256>>>(x);
    k_stft <<<dim3((T_+TS4-1)/TS4, B_), 256>>>(x, win);
    k_beam <<<dim3(F_, B_), 128>>>();
    k_istft<<<dim3((T_-1+NQ-1)/NQ, B_, 2), 288>>>(out);
}

// round 8
// speedup vs baseline: 6.3682x; 1.0352x over previous
#include <cuda_runtime.h>
#include <math.h>

#define B_    8
#define L_    160000
#define C_    4
#define NFFT_ 320
#define HOP_  160
#define T_    1001
#define F_    161
#define KTAP  6
#define NQ    7          // fused: output q-segments per block
#define TF    8          // fused: frames per block
#define TS4   4          // stft: frames per block
#define SVLEN (160*TS4 + 160)   // 800

// ---------------- scratch ----------------
__device__ float2 g_X [(size_t)B_*F_*T_*C_];    // STFT  [b][k][t][c]
__device__ float4 g_ssum[B_*32];
__device__ float4 g_smax[B_*32];
__device__ float4 g_smin[B_*32];

__constant__ float c_c95[10] = {0.95f, 0.0475f, 2.375e-3f, 1.1875e-4f, 5.9375e-6f,
                                2.96875e-7f, 1.484375e-8f, 7.421875e-10f,
                                3.7109375e-11f, 1.85546875e-12f};
__constant__ float c_p05[10] = {1.0f, 0.05f, 2.5e-3f, 1.25e-4f, 6.25e-6f,
                                3.125e-7f, 1.5625e-8f, 7.8125e-10f,
                                3.90625e-11f, 1.953125e-12f};

// ---------------- complex helpers ----------------
__device__ __forceinline__ float2 cadd(float2 a, float2 b){ return make_float2(a.x+b.x, a.y+b.y); }
__device__ __forceinline__ float2 csub(float2 a, float2 b){ return make_float2(a.x-b.x, a.y-b.y); }
__device__ __forceinline__ float2 cmul(float2 a, float2 b){ return make_float2(a.x*b.x-a.y*b.y, a.x*b.y+a.y*b.x); }
__device__ __forceinline__ float2 ccmul(float2 a, float2 b){ return make_float2(a.x*b.x+a.y*b.y, a.x*b.y-a.y*b.x); } // conj(a)*b
__device__ __forceinline__ float2 cmulc(float2 a, float2 b){ return make_float2(a.x*b.x+a.y*b.y, a.y*b.x-a.x*b.y); } // a*conj(b)
__device__ __forceinline__ float2 cscale(float s, float2 a){ return make_float2(s*a.x, s*a.y); }

// ---------------- single-pass stats ----------------
__global__ void k_stats(const float* __restrict__ x){
    int b = blockIdx.y, ch = blockIdx.x;
    int l0 = ch*5000;
    float4 s  = make_float4(0.f,0.f,0.f,0.f);
    float4 mx = make_float4(-1e30f,-1e30f,-1e30f,-1e30f);
    float4 mn = make_float4( 1e30f, 1e30f, 1e30f, 1e30f);
    for(int l = l0 + threadIdx.x; l < l0+5000; l += 256){
        float4 v = *(const float4*)(x + ((size_t)b*L_ + l)*C_);
        s.x += v.x; s.y += v.y; s.z += v.z; s.w += v.w;
        mx.x = fmaxf(mx.x,v.x); mx.y = fmaxf(mx.y,v.y); mx.z = fmaxf(mx.z,v.z); mx.w = fmaxf(mx.w,v.w);
        mn.x = fminf(mn.x,v.x); mn.y = fminf(mn.y,v.y); mn.z = fminf(mn.z,v.z); mn.w = fminf(mn.w,v.w);
    }
    __shared__ float4 rs[256], rx[256], rn[256];
    rs[threadIdx.x]=s; rx[threadIdx.x]=mx; rn[threadIdx.x]=mn; __syncthreads();
    for(int st = 128; st > 0; st >>= 1){
        if(threadIdx.x < st){
            float4 o = rs[threadIdx.x+st];
            rs[threadIdx.x].x += o.x; rs[threadIdx.x].y += o.y; rs[threadIdx.x].z += o.z; rs[threadIdx.x].w += o.w;
            float4 a = rx[threadIdx.x+st];
            rx[threadIdx.x].x = fmaxf(rx[threadIdx.x].x,a.x); rx[threadIdx.x].y = fmaxf(rx[threadIdx.x].y,a.y);
            rx[threadIdx.x].z = fmaxf(rx[threadIdx.x].z,a.z); rx[threadIdx.x].w = fmaxf(rx[threadIdx.x].w,a.w);
            float4 c = rn[threadIdx.x+st];
            rn[threadIdx.x].x = fminf(rn[threadIdx.x].x,c.x); rn[threadIdx.x].y = fminf(rn[threadIdx.x].y,c.y);
            rn[threadIdx.x].z = fminf(rn[threadIdx.x].z,c.z); rn[threadIdx.x].w = fminf(rn[threadIdx.x].w,c.w);
        }
        __syncthreads();
    }
    if(threadIdx.x == 0){
        g_ssum[b*32+ch] = rs[0]; g_smax[b*32+ch] = rx[0]; g_smin[b*32+ch] = rn[0];
    }
}

// ---------------- STFT: 4 frames/block, register radix DFT-16 + constant DFT-20 ----------------
__global__ void k_stft(const float* __restrict__ x, const float* __restrict__ win){
    const float C16[16] = { 1.f, 0.9238795325f, 0.7071067812f, 0.3826834324f, 0.f,
                           -0.3826834324f,-0.7071067812f,-0.9238795325f,-1.f,-0.9238795325f,
                           -0.7071067812f,-0.3826834324f, 0.f, 0.3826834324f, 0.7071067812f, 0.9238795325f };
    const float S16[16] = { 0.f, 0.3826834324f, 0.7071067812f, 0.9238795325f, 1.f,
                            0.9238795325f, 0.7071067812f, 0.3826834324f, 0.f,-0.3826834324f,
                           -0.7071067812f,-0.9238795325f,-1.f,-0.9238795325f,-0.7071067812f,-0.3826834324f };
    const float C20[20] = { 1.f, 0.9510565163f, 0.8090169944f, 0.5877852523f, 0.3090169944f,
                            0.f,-0.3090169944f,-0.5877852523f,-0.8090169944f,-0.9510565163f,
                           -1.f,-0.9510565163f,-0.8090169944f,-0.5877852523f,-0.3090169944f,
                            0.f, 0.3090169944f, 0.5877852523f, 0.8090169944f, 0.9510565163f };
    const float S20[20] = { 0.f, 0.3090169944f, 0.5877852523f, 0.8090169944f, 0.9510565163f,
                            1.f, 0.9510565163f, 0.8090169944f, 0.5877852523f, 0.3090169944f,
                            0.f,-0.3090169944f,-0.5877852523f,-0.8090169944f,-0.9510565163f,
                           -1.f,-0.9510565163f,-0.8090169944f,-0.5877852523f,-0.3090169944f };

    int blk = blockIdx.x, b = blockIdx.y;
    int tid = threadIdx.x;
    int t0 = blk*TS4;
    __shared__ float  sv[C_][SVLEN];
    __shared__ float  swin[NFFT_];
    __shared__ float2 sG[TS4][C_][9][20];
    __shared__ float  sMean[4];
    __shared__ float  sInv;

    if(tid < 32){
        float4 s  = g_ssum[b*32+tid];
        float4 mx = g_smax[b*32+tid];
        float4 mn = g_smin[b*32+tid];
        for(int o = 16; o; o >>= 1){
            s.x += __shfl_xor_sync(~0u, s.x, o); s.y += __shfl_xor_sync(~0u, s.y, o);
            s.z += __shfl_xor_sync(~0u, s.z, o); s.w += __shfl_xor_sync(~0u, s.w, o);
            mx.x = fmaxf(mx.x, __shfl_xor_sync(~0u, mx.x, o)); mx.y = fmaxf(mx.y, __shfl_xor_sync(~0u, mx.y, o));
            mx.z = fmaxf(mx.z, __shfl_xor_sync(~0u, mx.z, o)); mx.w = fmaxf(mx.w, __shfl_xor_sync(~0u, mx.w, o));
            mn.x = fminf(mn.x, __shfl_xor_sync(~0u, mn.x, o)); mn.y = fminf(mn.y, __shfl_xor_sync(~0u, mn.y, o));
            mn.z = fminf(mn.z, __shfl_xor_sync(~0u, mn.z, o)); mn.w = fminf(mn.w, __shfl_xor_sync(~0u, mn.w, o));
        }
        if(tid == 0){
            float m0 = s.x/(float)L_, m1 = s.y/(float)L_, m2 = s.z/(float)L_, m3 = s.w/(float)L_;
            float a = fmaxf(fmaxf(mx.x-m0, m0-mn.x), fmaxf(mx.y-m1, m1-mn.y));
            a = fmaxf(a, fmaxf(fmaxf(mx.z-m2, m2-mn.z), fmaxf(mx.w-m3, m3-mn.w)));
            sMean[0]=m0; sMean[1]=m1; sMean[2]=m2; sMean[3]=m3; sInv = 1.0f/a;
        }
    }
    for(int i = tid; i < NFFT_; i += 256) swin[i] = win[i];
    __syncthreads();

    {
        float m0 = sMean[0], m1 = sMean[1], m2 = sMean[2], m3 = sMean[3], inv = sInv;
        for(int i = tid; i < SVLEN; i += 256){
            int l = t0*HOP_ + i - (NFFT_/2);
            if(l < 0) l = -l;
            else if(l >= L_) l = 2*L_ - 2 - l;
            float4 v = *(const float4*)(x + ((size_t)b*L_ + l)*C_);
            sv[0][i] = (v.x-m0)*inv; sv[1][i] = (v.y-m1)*inv;
            sv[2][i] = (v.z-m2)*inv; sv[3][i] = (v.w-m3)*inv;
        }
    }
    __syncthreads();

    for(int task = tid; task < TS4*C_*20; task += 256){
        int r = task % 20;
        int c = (task/20) & 3;
        int f = task/80;
        int base = f*HOP_ + r;
        float v[16];
        #pragma unroll
        for(int q = 0; q < 16; q++) v[q] = sv[c][base + 20*q] * swin[20*q + r];
        float2 Bq[4][4];
        #pragma unroll
        for(int qb = 0; qb < 4; qb++){
            float v0=v[qb], v1=v[4+qb], v2=v[8+qb], v3=v[12+qb];
            float s0=v0+v2, d0=v0-v2, s1=v1+v3, d1=v1-v3;
            Bq[qb][0] = make_float2(s0+s1, 0.f);
            Bq[qb][2] = make_float2(s0-s1, 0.f);
            Bq[qb][1] = make_float2(d0, -d1);
            Bq[qb][3] = make_float2(d0,  d1);
        }
        float sn, cs; sincospif(-(float)r/160.0f, &sn, &cs);
        float2 step = make_float2(cs, sn), w = make_float2(1.f, 0.f);
        #pragma unroll
        for(int m = 0; m < 9; m++){
            float2 acc = Bq[0][m&3];
            #pragma unroll
            for(int qb = 1; qb < 4; qb++){
                int j = (qb*m) & 15;
                float2 y = Bq[qb][m&3];
                acc.x += y.x*C16[j] + y.y*S16[j];
                acc.y += y.y*C16[j] - y.x*S16[j];
            }
            sG[f][c][m][r] = cmul(acc, w);
            w = cmul(w, step);
        }
    }
    __syncthreads();

    for(int task = tid; task < TS4*C_*16; task += 256){
        int m = task & 15;
        int c = (task >> 4) & 3;
        int f = task >> 6;
        int t = t0 + f;
        if(t >= T_) continue;
        float2 y[20];
        if(m <= 8){
            #pragma unroll
            for(int r = 0; r < 20; r++) y[r] = sG[f][c][m][r];
        } else {
            int mm = 16 - m;
            #pragma unroll
            for(int r = 0; r < 20; r++){
                float2 g = sG[f][c][mm][r];
                float gr = g.x, gi = -g.y;
                y[r].x = gr*C20[r] + gi*S20[r];
                y[r].y = gi*C20[r] - gr*S20[r];
            }
        }
        float2 D[5][4];
        #pragma unroll
        for(int r2 = 0; r2 < 5; r2++){
            float2 y0=y[r2], y1=y[5+r2], y2=y[10+r2], y3=y[15+r2];
            float2 s0=cadd(y0,y2), d0=csub(y0,y2), s1=cadd(y1,y3), d1=csub(y1,y3);
            D[r2][0] = cadd(s0,s1);
            D[r2][2] = csub(s0,s1);
            D[r2][1] = make_float2(d0.x + d1.y, d0.y - d1.x);
            D[r2][3] = make_float2(d0.x - d1.y, d0.y + d1.x);
        }
        int amax = (m == 0) ? 10 : 9;
        #pragma unroll
        for(int a = 0; a <= 10; a++){
            if(a > amax) break;
            float2 acc = D[0][a&3];
            #pragma unroll
            for(int r2 = 1; r2 < 5; r2++){
                int j = (a*r2) % 20;
                float2 dd = D[r2][a&3];
                acc.x += dd.x*C20[j] + dd.y*S20[j];
                acc.y += dd.y*C20[j] - dd.x*S20[j];
            }
            int k = 16*a + m;
            g_X[(((size_t)b*F_ + k)*T_ + t)*C_ + c] = acc;
        }
    }
}

// ---------------- fused MVDR beam + ISTFT + OLA ----------------
struct LDLf { float iD0,iD1,iD2,iD3; float2 L10,L20,L30,L21,L31,L32; };

__device__ __forceinline__ float2 mvdr_beam2(const LDLf& f,
    float2 h1, float2 h2, float2 h3,          // h0 = 1
    float2 X0, float2 X1, float2 X2, float2 X3)
{
    float2 z1 = csub(h1, f.L10);
    float2 z2 = csub(csub(h2, f.L20), cmul(f.L21, z1));
    float2 z3 = csub(csub(csub(h3, f.L30), cmul(f.L31, z1)), cmul(f.L32, z2));
    float2 y3 = cscale(f.iD3, z3);
    float2 y2 = csub(cscale(f.iD2, z2), ccmul(f.L32, y3));
    float2 y1 = csub(csub(cscale(f.iD1, z1), ccmul(f.L21, y2)), ccmul(f.L31, y3));
    float2 y0 = csub(csub(csub(make_float2(f.iD0, 0.f), ccmul(f.L10, y1)), ccmul(f.L20, y2)), ccmul(f.L30, y3));
    float den = y0.x + (h1.x*y1.x + h1.y*y1.y) + (h2.x*y2.x + h2.y*y2.y) + (h3.x*y3.x + h3.y*y3.y);
    float2 s  = cadd(cadd(ccmul(y0,X0), ccmul(y1,X1)), cadd(ccmul(y2,X2), ccmul(y3,X3)));
    float inv = 1.0f/den;
    return make_float2(s.x*inv, s.y*inv);
}

#define SY_BYTES (2*TF*162*8)     // 20736
#define SFR_BYTES (2*TF*322*4)    // 20608

__global__ void __launch_bounds__(192) k_bistft(float* __restrict__ out){
    const float C20[20] = { 1.f, 0.9510565163f, 0.8090169944f, 0.5877852523f, 0.3090169944f,
                            0.f,-0.3090169944f,-0.5877852523f,-0.8090169944f,-0.9510565163f,
                           -1.f,-0.9510565163f,-0.8090169944f,-0.5877852523f,-0.3090169944f,
                            0.f, 0.3090169944f, 0.5877852523f, 0.8090169944f, 0.9510565163f };
    const float S20[20] = { 0.f, 0.3090169944f, 0.5877852523f, 0.8090169944f, 0.9510565163f,
                            1.f, 0.9510565163f, 0.8090169944f, 0.5877852523f, 0.3090169944f,
                            0.f,-0.3090169944f,-0.5877852523f,-0.8090169944f,-0.9510565163f,
                           -1.f,-0.9510565163f,-0.8090169944f,-0.5877852523f,-0.3090169944f };
    const float C16[16] = { 1.f, 0.9238795325f, 0.7071067812f, 0.3826834324f, 0.f,
                           -0.3826834324f,-0.7071067812f,-0.9238795325f,-1.f,-0.9238795325f,
                           -0.7071067812f,-0.3826834324f, 0.f, 0.3826834324f, 0.7071067812f, 0.9238795325f };
    const float S16[16] = { 0.f, 0.3826834324f, 0.7071067812f, 0.9238795325f, 1.f,
                            0.9238795325f, 0.7071067812f, 0.3826834324f, 0.f,-0.3826834324f,
                           -0.7071067812f,-0.9238795325f,-1.f,-0.9238795325f,-0.7071067812f,-0.3826834324f };

    int blk = blockIdx.x, b = blockIdx.y;
    int tid = threadIdx.x;
    int t0  = blk*NQ;

    __shared__ float2 sH[2][9][20][TF+1];
    __shared__ __align__(16) char pool[SY_BYTES > SFR_BYTES ? SY_BYTES : SFR_BYTES];
    float2* sY  = (float2*)pool;   // [ (beam*TF+f)*162 + k ]
    float*  sFr = (float*)pool;    // [ (beam*TF+f)*322 + n ]  (aliases sY, used after)

    // ======== phase 1: beam (161 threads, serial IIR chain over TF frames) ========
    if(tid < F_){
        int k = tid;
        const float4* gx = (const float4*)g_X + ((size_t)(b*F_ + k))*T_*2;

        const float phi = (float)(6.283185307179586 * 50.0 * 0.027 * 0.6427876096865393 / 340.0);
        float ang = phi * (float)k;
        float s1, c1; sincosf(ang, &s1, &c1);
        float c2 = c1*c1 - s1*s1, s2 = 2.f*c1*s1;
        float c3 = c2*c1 - s2*s1, s3 = s2*c1 + c2*s1;

        float d0=0,d1=0,d2=0,d3=0;
        float2 m10={0,0}, m20={0,0}, m21={0,0}, m30={0,0}, m31={0,0}, m32={0,0};

        int tw = t0 - 1;
        if(tw >= 0){
            #pragma unroll
            for(int j = 0; j < KTAP; j++){
                int s = tw - j;
                if(s < 0) break;
                float cf = (s == 0) ? c_p05[tw] : c_c95[j];
                float4 a = gx[(size_t)s*2], bb = gx[(size_t)s*2+1];
                float2 y0 = make_float2(a.x,a.y), y1 = make_float2(a.z,a.w);
                float2 y2 = make_float2(bb.x,bb.y), y3 = make_float2(bb.z,bb.w);
                d0 += cf*(y0.x*y0.x + y0.y*y0.y);
                d1 += cf*(y1.x*y1.x + y1.y*y1.y);
                d2 += cf*(y2.x*y2.x + y2.y*y2.y);
                d3 += cf*(y3.x*y3.x + y3.y*y3.y);
                m10 = cadd(m10, cscale(cf, cmulc(y1,y0)));
                m20 = cadd(m20, cscale(cf, cmulc(y2,y0)));
                m21 = cadd(m21, cscale(cf, cmulc(y2,y1)));
                m30 = cadd(m30, cscale(cf, cmulc(y3,y0)));
                m31 = cadd(m31, cscale(cf, cmulc(y3,y1)));
                m32 = cadd(m32, cscale(cf, cmulc(y3,y2)));
            }
        }

        #pragma unroll
        for(int i = 0; i < TF; i++){
            int t = t0 + i;
            if(t < T_){
                float4 xa = gx[(size_t)t*2], xb = gx[(size_t)t*2+1];
                float2 X0 = make_float2(xa.x,xa.y), X1 = make_float2(xa.z,xa.w);
                float2 X2 = make_float2(xb.x,xb.y), X3 = make_float2(xb.z,xb.w);

                if(t == 0){
                    d0 = X0.x*X0.x + X0.y*X0.y;
                    d1 = X1.x*X1.x + X1.y*X1.y;
                    d2 = X2.x*X2.x + X2.y*X2.y;
                    d3 = X3.x*X3.x + X3.y*X3.y;
                    m10 = cmulc(X1,X0); m20 = cmulc(X2,X0); m21 = cmulc(X2,X1);
                    m30 = cmulc(X3,X0); m31 = cmulc(X3,X1); m32 = cmulc(X3,X2);
                } else {
                    d0 = 0.05f*d0 + 0.95f*(X0.x*X0.x + X0.y*X0.y);
                    d1 = 0.05f*d1 + 0.95f*(X1.x*X1.x + X1.y*X1.y);
                    d2 = 0.05f*d2 + 0.95f*(X2.x*X2.x + X2.y*X2.y);
                    d3 = 0.05f*d3 + 0.95f*(X3.x*X3.x + X3.y*X3.y);
                    m10 = cadd(cscale(0.05f,m10), cscale(0.95f, cmulc(X1,X0)));
                    m20 = cadd(cscale(0.05f,m20), cscale(0.95f, cmulc(X2,X0)));
                    m21 = cadd(cscale(0.05f,m21), cscale(0.95f, cmulc(X2,X1)));
                    m30 = cadd(cscale(0.05f,m30), cscale(0.95f, cmulc(X3,X0)));
                    m31 = cadd(cscale(0.05f,m31), cscale(0.95f, cmulc(X3,X1)));
                    m32 = cadd(cscale(0.05f,m32), cscale(0.95f, cmulc(X3,X2)));
                }

                float tr4 = 0.25f*(d0+d1+d2+d3);
                float a0 = d0+tr4, a1 = d1+tr4, a2 = d2+tr4, a3 = d3+tr4;

                LDLf f;
                f.iD0 = 1.0f/a0;
                f.L10 = cscale(f.iD0, m10); f.L20 = cscale(f.iD0, m20); f.L30 = cscale(f.iD0, m30);
                float D1 = a1 - (m10.x*f.L10.x + m10.y*f.L10.y);
                f.iD1 = 1.0f/D1;
                float2 t21 = csub(m21, cmulc(m20, f.L10));
                f.L21 = cscale(f.iD1, t21);
                float2 t31 = csub(m31, cmulc(m30, f.L10));
                f.L31 = cscale(f.iD1, t31);
                float D2 = a2 - (m20.x*f.L20.x + m20.y*f.L20.y) - (t21.x*f.L21.x + t21.y*f.L21.y);
                f.iD2 = 1.0f/D2;
                float2 t32 = csub(csub(m32, cmulc(m30, f.L20)), cmulc(t31, f.L21));
                f.L32 = cscale(f.iD2, t32);
                float D3 = a3 - (m30.x*f.L30.x + m30.y*f.L30.y)
                              - (t31.x*f.L31.x + t31.y*f.L31.y)
                              - (t32.x*f.L32.x + t32.y*f.L32.y);
                f.iD3 = 1.0f/D3;

                float2 o1 = mvdr_beam2(f, make_float2(c1,-s1), make_float2(c2,-s2), make_float2(c3,-s3),
                                       X0, X1, X2, X3);
                float2 o2 = mvdr_beam2(f, make_float2(c1, s1), make_float2(c2, s2), make_float2(c3, s3),
                                       X0, X1, X2, X3);
                sY[(0*TF+i)*162 + k] = o1;
                sY[(1*TF+i)*162 + k] = o2;
            } else {
                sY[(0*TF+i)*162 + k] = make_float2(0.f,0.f);
                sY[(1*TF+i)*162 + k] = make_float2(0.f,0.f);
            }
        }
    }
    __syncthreads();

    // ======== phase 2 (stage A): per (beam,k1,f) inverse DFT-20 -> sH ========
    if(tid < 2*9*TF){
        int beam = tid / (9*TF);
        int r    = tid % (9*TF);
        int k1 = r / TF, f = r % TF;
        const float2* yrow = sY + (beam*TF + f)*162;
        float2 z[20];
        #pragma unroll
        for(int k2 = 0; k2 < 20; k2++){
            int kk = 16*k2 + k1;
            float2 v;
            if(kk <= 160){
                v = yrow[kk];
                if(k1 == 0 && (k2 == 0 || k2 == 10)) v.y = 0.f;
            } else {
                v = yrow[320-kk];
                v.y = -v.y;
            }
            z[k2] = v;
        }
        float2 Y[5][4];
        #pragma unroll
        for(int bq = 0; bq < 5; bq++){
            float2 z0=z[bq], z1=z[bq+5], z2=z[bq+10], z3=z[bq+15];
            float2 s0=cadd(z0,z2), s1=csub(z0,z2), s2=cadd(z1,z3), s3=csub(z1,z3);
            Y[bq][0] = cadd(s0,s2);
            Y[bq][2] = csub(s0,s2);
            Y[bq][1] = make_float2(s1.x - s3.y, s1.y + s3.x);
            Y[bq][3] = make_float2(s1.x + s3.y, s1.y - s3.x);
        }
        float sc = (k1==0 || k1==8) ? 1.f : 2.f;
        #pragma unroll
        for(int p = 0; p < 20; p++){
            float2 acc = Y[0][p&3];
            #pragma unroll
            for(int bq = 1; bq < 5; bq++){
                float cw = C20[(bq*p)%20], sw = S20[(bq*p)%20];
                float2 y = Y[bq][p&3];
                acc.x += cw*y.x - sw*y.y;
                acc.y += cw*y.y + sw*y.x;
            }
            sH[beam][k1][p][f] = make_float2(sc*acc.x, sc*acc.y);
        }
    }
    __syncthreads();

    // ======== phase 3 (stage B): twiddle + 9-term DFT-16 -> sFr (aliases sY) ========
    for(int task = tid; task < 2*20*TF; task += 192){
        int beam = task / (20*TF);
        int r    = task % (20*TF);
        int pm = r / TF, f = r % TF;
        float sn, cs; sincospif((float)pm/160.0f, &sn, &cs);
        float2 wst = make_float2(cs, sn), w = make_float2(1.f, 0.f);
        float2 a[9];
        a[0] = sH[beam][0][pm][f];
        #pragma unroll
        for(int k1 = 1; k1 < 9; k1++){
            w = cmul(w, wst);
            a[k1] = cmul(sH[beam][k1][pm][f], w);
        }
        float* frow = sFr + (beam*TF + f)*322;
        #pragma unroll
        for(int u = 0; u < 16; u++){
            float acc = a[0].x;
            #pragma unroll
            for(int k1 = 1; k1 < 9; k1++){
                int j = (k1*u) & 15;
                acc += a[k1].x*C16[j] - a[k1].y*S16[j];
            }
            frow[20*u + pm] = acc * (1.0f/640.0f);
        }
    }
    __syncthreads();

    // ======== phase 4: OLA output ========
    int qmax = min(t0 + NQ, T_ - 1);
    int nq = qmax - t0;
    for(int task = tid; task < 2*nq*80; task += 192){
        int beam = task / (nq*80);
        int r2   = task % (nq*80);
        int qi = r2 / 80;
        int rr = (r2 % 80)*2;
        int q  = t0 + 1 + qi;
        int fq = qi + 1;
        const float* fa = sFr + (beam*TF + fq)*322;
        const float* fb = sFr + (beam*TF + fq - 1)*322;
        float v0 = fa[rr]   + fb[160+rr];
        float v1 = fa[rr+1] + fb[161+rr];
        *(float2*)(out + (size_t)(beam*B_+b)*L_ + (size_t)(q-1)*160 + rr) = make_float2(v0, v1);
    }
}

// ---------------- launch ----------------
extern "C" void kernel_launch(void* const* d_in, const int* in_sizes, int n_in,
                              void* d_out, int out_size){
    const float* x   = (const float*)d_in[0];
    const float* win = (const float*)d_in[1];
    float* out = (float*)d_out;

    k_stats <<<dim3(32, B_), 256>>>(x);
    k_stft  <<<dim3((T_+TS4-1)/TS4, B_), 256>>>(x, win);
    k_bistft<<<dim3((T_-1+NQ-1)/NQ, B_), 192>>>(out);
}

// round 9
// speedup vs baseline: 6.3964x; 1.0044x over previous
#include <cuda_runtime.h>
#include <math.h>

#define B_    8
#define L_    160000
#define C_    4
#define NFFT_ 320
#define HOP_  160
#define T_    1001
#define F_    161
#define KTAP  6
#define NQ    7          // fused: output q-segments per block
#define TF    8          // fused: frames per block
#define TS4   4          // stft: frames per block
#define SVLEN (160*TS4 + 160)   // 800
#define NCH   125        // stats chunks per batch
#define CHL   1280       // samples per chunk (5 x 256)

// ---------------- scratch ----------------
__device__ float2 g_X [(size_t)B_*F_*T_*C_];    // STFT  [b][k][t][c]
__device__ float4 g_ssum[B_*NCH];
__device__ float4 g_smax[B_*NCH];
__device__ float4 g_smin[B_*NCH];

__constant__ float c_c95[10] = {0.95f, 0.0475f, 2.375e-3f, 1.1875e-4f, 5.9375e-6f,
                                2.96875e-7f, 1.484375e-8f, 7.421875e-10f,
                                3.7109375e-11f, 1.85546875e-12f};
__constant__ float c_p05[10] = {1.0f, 0.05f, 2.5e-3f, 1.25e-4f, 6.25e-6f,
                                3.125e-7f, 1.5625e-8f, 7.8125e-10f,
                                3.90625e-11f, 1.953125e-12f};

// ---------------- complex helpers ----------------
__device__ __forceinline__ float2 cadd(float2 a, float2 b){ return make_float2(a.x+b.x, a.y+b.y); }
__device__ __forceinline__ float2 csub(float2 a, float2 b){ return make_float2(a.x-b.x, a.y-b.y); }
__device__ __forceinline__ float2 cmul(float2 a, float2 b){ return make_float2(a.x*b.x-a.y*b.y, a.x*b.y+a.y*b.x); }
__device__ __forceinline__ float2 ccmul(float2 a, float2 b){ return make_float2(a.x*b.x+a.y*b.y, a.x*b.y-a.y*b.x); } // conj(a)*b
__device__ __forceinline__ float2 cmulc(float2 a, float2 b){ return make_float2(a.x*b.x+a.y*b.y, a.y*b.x-a.x*b.y); } // a*conj(b)
__device__ __forceinline__ float2 cscale(float s, float2 a){ return make_float2(s*a.x, s*a.y); }

// ---------------- stats: 1000 blocks, 5 unrolled loads/thread, shfl reduce ----------------
__global__ void k_stats(const float* __restrict__ x){
    int b = blockIdx.y, ch = blockIdx.x;
    int tid = threadIdx.x;
    const float4* px = (const float4*)(x + (size_t)b*L_*C_) + ch*CHL + tid;

    float4 v0 = px[0], v1 = px[256], v2 = px[512], v3 = px[768], v4 = px[1024];

    float4 s, mx, mn;
    s.x = v0.x+v1.x+v2.x+v3.x+v4.x; s.y = v0.y+v1.y+v2.y+v3.y+v4.y;
    s.z = v0.z+v1.z+v2.z+v3.z+v4.z; s.w = v0.w+v1.w+v2.w+v3.w+v4.w;
    mx.x = fmaxf(fmaxf(fmaxf(v0.x,v1.x),fmaxf(v2.x,v3.x)),v4.x);
    mx.y = fmaxf(fmaxf(fmaxf(v0.y,v1.y),fmaxf(v2.y,v3.y)),v4.y);
    mx.z = fmaxf(fmaxf(fmaxf(v0.z,v1.z),fmaxf(v2.z,v3.z)),v4.z);
    mx.w = fmaxf(fmaxf(fmaxf(v0.w,v1.w),fmaxf(v2.w,v3.w)),v4.w);
    mn.x = fminf(fminf(fminf(v0.x,v1.x),fminf(v2.x,v3.x)),v4.x);
    mn.y = fminf(fminf(fminf(v0.y,v1.y),fminf(v2.y,v3.y)),v4.y);
    mn.z = fminf(fminf(fminf(v0.z,v1.z),fminf(v2.z,v3.z)),v4.z);
    mn.w = fminf(fminf(fminf(v0.w,v1.w),fminf(v2.w,v3.w)),v4.w);

    // warp shfl reduce
    #pragma unroll
    for(int o = 16; o; o >>= 1){
        s.x += __shfl_xor_sync(~0u, s.x, o); s.y += __shfl_xor_sync(~0u, s.y, o);
        s.z += __shfl_xor_sync(~0u, s.z, o); s.w += __shfl_xor_sync(~0u, s.w, o);
        mx.x = fmaxf(mx.x, __shfl_xor_sync(~0u, mx.x, o)); mx.y = fmaxf(mx.y, __shfl_xor_sync(~0u, mx.y, o));
        mx.z = fmaxf(mx.z, __shfl_xor_sync(~0u, mx.z, o)); mx.w = fmaxf(mx.w, __shfl_xor_sync(~0u, mx.w, o));
        mn.x = fminf(mn.x, __shfl_xor_sync(~0u, mn.x, o)); mn.y = fminf(mn.y, __shfl_xor_sync(~0u, mn.y, o));
        mn.z = fminf(mn.z, __shfl_xor_sync(~0u, mn.z, o)); mn.w = fminf(mn.w, __shfl_xor_sync(~0u, mn.w, o));
    }

    __shared__ float4 ps[8], pxm[8], pnm[8];
    int w = tid >> 5, lane = tid & 31;
    if(lane == 0){ ps[w] = s; pxm[w] = mx; pnm[w] = mn; }
    __syncthreads();
    if(tid < 8){
        s = ps[tid]; mx = pxm[tid]; mn = pnm[tid];
        #pragma unroll
        for(int o = 4; o; o >>= 1){
            s.x += __shfl_xor_sync(0xff, s.x, o); s.y += __shfl_xor_sync(0xff, s.y, o);
            s.z += __shfl_xor_sync(0xff, s.z, o); s.w += __shfl_xor_sync(0xff, s.w, o);
            mx.x = fmaxf(mx.x, __shfl_xor_sync(0xff, mx.x, o)); mx.y = fmaxf(mx.y, __shfl_xor_sync(0xff, mx.y, o));
            mx.z = fmaxf(mx.z, __shfl_xor_sync(0xff, mx.z, o)); mx.w = fmaxf(mx.w, __shfl_xor_sync(0xff, mx.w, o));
            mn.x = fminf(mn.x, __shfl_xor_sync(0xff, mn.x, o)); mn.y = fminf(mn.y, __shfl_xor_sync(0xff, mn.y, o));
            mn.z = fminf(mn.z, __shfl_xor_sync(0xff, mn.z, o)); mn.w = fminf(mn.w, __shfl_xor_sync(0xff, mn.w, o));
        }
        if(tid == 0){
            g_ssum[b*NCH+ch] = s; g_smax[b*NCH+ch] = mx; g_smin[b*NCH+ch] = mn;
        }
    }
}

// ---------------- STFT: 4 frames/block, register radix DFT-16 + constant DFT-20 ----------------
__global__ void k_stft(const float* __restrict__ x, const float* __restrict__ win){
    const float C16[16] = { 1.f, 0.9238795325f, 0.7071067812f, 0.3826834324f, 0.f,
                           -0.3826834324f,-0.7071067812f,-0.9238795325f,-1.f,-0.9238795325f,
                           -0.7071067812f,-0.3826834324f, 0.f, 0.3826834324f, 0.7071067812f, 0.9238795325f };
    const float S16[16] = { 0.f, 0.3826834324f, 0.7071067812f, 0.9238795325f, 1.f,
                            0.9238795325f, 0.7071067812f, 0.3826834324f, 0.f,-0.3826834324f,
                           -0.7071067812f,-0.9238795325f,-1.f,-0.9238795325f,-0.7071067812f,-0.3826834324f };
    const float C20[20] = { 1.f, 0.9510565163f, 0.8090169944f, 0.5877852523f, 0.3090169944f,
                            0.f,-0.3090169944f,-0.5877852523f,-0.8090169944f,-0.9510565163f,
                           -1.f,-0.9510565163f,-0.8090169944f,-0.5877852523f,-0.3090169944f,
                            0.f, 0.3090169944f, 0.5877852523f, 0.8090169944f, 0.9510565163f };
    const float S20[20] = { 0.f, 0.3090169944f, 0.5877852523f, 0.8090169944f, 0.9510565163f,
                            1.f, 0.9510565163f, 0.8090169944f, 0.5877852523f, 0.3090169944f,
                            0.f,-0.3090169944f,-0.5877852523f,-0.8090169944f,-0.9510565163f,
                           -1.f,-0.9510565163f,-0.8090169944f,-0.5877852523f,-0.3090169944f };

    int blk = blockIdx.x, b = blockIdx.y;
    int tid = threadIdx.x;
    int t0 = blk*TS4;
    __shared__ float  sv[C_][SVLEN];
    __shared__ float  swin[NFFT_];
    __shared__ float2 sG[TS4][C_][9][20];
    __shared__ float  sMean[4];
    __shared__ float  sInv;

    if(tid < 32){
        float4 s  = make_float4(0.f,0.f,0.f,0.f);
        float4 mx = make_float4(-1e30f,-1e30f,-1e30f,-1e30f);
        float4 mn = make_float4( 1e30f, 1e30f, 1e30f, 1e30f);
        for(int i = tid; i < NCH; i += 32){
            float4 a = g_ssum[b*NCH+i];
            s.x += a.x; s.y += a.y; s.z += a.z; s.w += a.w;
            float4 c = g_smax[b*NCH+i];
            mx.x = fmaxf(mx.x,c.x); mx.y = fmaxf(mx.y,c.y); mx.z = fmaxf(mx.z,c.z); mx.w = fmaxf(mx.w,c.w);
            float4 d = g_smin[b*NCH+i];
            mn.x = fminf(mn.x,d.x); mn.y = fminf(mn.y,d.y); mn.z = fminf(mn.z,d.z); mn.w = fminf(mn.w,d.w);
        }
        for(int o = 16; o; o >>= 1){
            s.x += __shfl_xor_sync(~0u, s.x, o); s.y += __shfl_xor_sync(~0u, s.y, o);
            s.z += __shfl_xor_sync(~0u, s.z, o); s.w += __shfl_xor_sync(~0u, s.w, o);
            mx.x = fmaxf(mx.x, __shfl_xor_sync(~0u, mx.x, o)); mx.y = fmaxf(mx.y, __shfl_xor_sync(~0u, mx.y, o));
            mx.z = fmaxf(mx.z, __shfl_xor_sync(~0u, mx.z, o)); mx.w = fmaxf(mx.w, __shfl_xor_sync(~0u, mx.w, o));
            mn.x = fminf(mn.x, __shfl_xor_sync(~0u, mn.x, o)); mn.y = fminf(mn.y, __shfl_xor_sync(~0u, mn.y, o));
            mn.z = fminf(mn.z, __shfl_xor_sync(~0u, mn.z, o)); mn.w = fminf(mn.w, __shfl_xor_sync(~0u, mn.w, o));
        }
        if(tid == 0){
            float m0 = s.x/(float)L_, m1 = s.y/(float)L_, m2 = s.z/(float)L_, m3 = s.w/(float)L_;
            float a = fmaxf(fmaxf(mx.x-m0, m0-mn.x), fmaxf(mx.y-m1, m1-mn.y));
            a = fmaxf(a, fmaxf(fmaxf(mx.z-m2, m2-mn.z), fmaxf(mx.w-m3, m3-mn.w)));
            sMean[0]=m0; sMean[1]=m1; sMean[2]=m2; sMean[3]=m3; sInv = 1.0f/a;
        }
    }
    for(int i = tid; i < NFFT_; i += 256) swin[i] = win[i];
    __syncthreads();

    {
        float m0 = sMean[0], m1 = sMean[1], m2 = sMean[2], m3 = sMean[3], inv = sInv;
        for(int i = tid; i < SVLEN; i += 256){
            int l = t0*HOP_ + i - (NFFT_/2);
            if(l < 0) l = -l;
            else if(l >= L_) l = 2*L_ - 2 - l;
            float4 v = *(const float4*)(x + ((size_t)b*L_ + l)*C_);
            sv[0][i] = (v.x-m0)*inv; sv[1][i] = (v.y-m1)*inv;
            sv[2][i] = (v.z-m2)*inv; sv[3][i] = (v.w-m3)*inv;
        }
    }
    __syncthreads();

    for(int task = tid; task < TS4*C_*20; task += 256){
        int r = task % 20;
        int c = (task/20) & 3;
        int f = task/80;
        int base = f*HOP_ + r;
        float v[16];
        #pragma unroll
        for(int q = 0; q < 16; q++) v[q] = sv[c][base + 20*q] * swin[20*q + r];
        float2 Bq[4][4];
        #pragma unroll
        for(int qb = 0; qb < 4; qb++){
            float v0=v[qb], v1=v[4+qb], v2=v[8+qb], v3=v[12+qb];
            float s0=v0+v2, d0=v0-v2, s1=v1+v3, d1=v1-v3;
            Bq[qb][0] = make_float2(s0+s1, 0.f);
            Bq[qb][2] = make_float2(s0-s1, 0.f);
            Bq[qb][1] = make_float2(d0, -d1);
            Bq[qb][3] = make_float2(d0,  d1);
        }
        float sn, cs; sincospif(-(float)r/160.0f, &sn, &cs);
        float2 step = make_float2(cs, sn), w = make_float2(1.f, 0.f);
        #pragma unroll
        for(int m = 0; m < 9; m++){
            float2 acc = Bq[0][m&3];
            #pragma unroll
            for(int qb = 1; qb < 4; qb++){
                int j = (qb*m) & 15;
                float2 y = Bq[qb][m&3];
                acc.x += y.x*C16[j] + y.y*S16[j];
                acc.y += y.y*C16[j] - y.x*S16[j];
            }
            sG[f][c][m][r] = cmul(acc, w);
            w = cmul(w, step);
        }
    }
    __syncthreads();

    for(int task = tid; task < TS4*C_*16; task += 256){
        int m = task & 15;
        int c = (task >> 4) & 3;
        int f = task >> 6;
        int t = t0 + f;
        if(t >= T_) continue;
        float2 y[20];
        if(m <= 8){
            #pragma unroll
            for(int r = 0; r < 20; r++) y[r] = sG[f][c][m][r];
        } else {
            int mm = 16 - m;
            #pragma unroll
            for(int r = 0; r < 20; r++){
                float2 g = sG[f][c][mm][r];
                float gr = g.x, gi = -g.y;
                y[r].x = gr*C20[r] + gi*S20[r];
                y[r].y = gi*C20[r] - gr*S20[r];
            }
        }
        float2 D[5][4];
        #pragma unroll
        for(int r2 = 0; r2 < 5; r2++){
            float2 y0=y[r2], y1=y[5+r2], y2=y[10+r2], y3=y[15+r2];
            float2 s0=cadd(y0,y2), d0=csub(y0,y2), s1=cadd(y1,y3), d1=csub(y1,y3);
            D[r2][0] = cadd(s0,s1);
            D[r2][2] = csub(s0,s1);
            D[r2][1] = make_float2(d0.x + d1.y, d0.y - d1.x);
            D[r2][3] = make_float2(d0.x - d1.y, d0.y + d1.x);
        }
        int amax = (m == 0) ? 10 : 9;
        #pragma unroll
        for(int a = 0; a <= 10; a++){
            if(a > amax) break;
            float2 acc = D[0][a&3];
            #pragma unroll
            for(int r2 = 1; r2 < 5; r2++){
                int j = (a*r2) % 20;
                float2 dd = D[r2][a&3];
                acc.x += dd.x*C20[j] + dd.y*S20[j];
                acc.y += dd.y*C20[j] - dd.x*S20[j];
            }
            int k = 16*a + m;
            g_X[(((size_t)b*F_ + k)*T_ + t)*C_ + c] = acc;
        }
    }
}

// ---------------- fused MVDR beam + ISTFT + OLA ----------------
struct LDLf { float iD0,iD1,iD2,iD3; float2 L10,L20,L30,L21,L31,L32; };

__device__ __forceinline__ float2 mvdr_beam2(const LDLf& f,
    float2 h1, float2 h2, float2 h3,          // h0 = 1
    float2 X0, float2 X1, float2 X2, float2 X3)
{
    float2 z1 = csub(h1, f.L10);
    float2 z2 = csub(csub(h2, f.L20), cmul(f.L21, z1));
    float2 z3 = csub(csub(csub(h3, f.L30), cmul(f.L31, z1)), cmul(f.L32, z2));
    float2 y3 = cscale(f.iD3, z3);
    float2 y2 = csub(cscale(f.iD2, z2), ccmul(f.L32, y3));
    float2 y1 = csub(csub(cscale(f.iD1, z1), ccmul(f.L21, y2)), ccmul(f.L31, y3));
    float2 y0 = csub(csub(csub(make_float2(f.iD0, 0.f), ccmul(f.L10, y1)), ccmul(f.L20, y2)), ccmul(f.L30, y3));
    float den = y0.x + (h1.x*y1.x + h1.y*y1.y) + (h2.x*y2.x + h2.y*y2.y) + (h3.x*y3.x + h3.y*y3.y);
    float2 s  = cadd(cadd(ccmul(y0,X0), ccmul(y1,X1)), cadd(ccmul(y2,X2), ccmul(y3,X3)));
    float inv = 1.0f/den;
    return make_float2(s.x*inv, s.y*inv);
}

#define SY_BYTES (2*TF*162*8)     // 20736
#define SFR_BYTES (2*TF*322*4)    // 20608

__global__ void __launch_bounds__(192) k_bistft(float* __restrict__ out){
    const float C20[20] = { 1.f, 0.9510565163f, 0.8090169944f, 0.5877852523f, 0.3090169944f,
                            0.f,-0.3090169944f,-0.5877852523f,-0.8090169944f,-0.9510565163f,
                           -1.f,-0.9510565163f,-0.8090169944f,-0.5877852523f,-0.3090169944f,
                            0.f, 0.3090169944f, 0.5877852523f, 0.8090169944f, 0.9510565163f };
    const float S20[20] = { 0.f, 0.3090169944f, 0.5877852523f, 0.8090169944f, 0.9510565163f,
                            1.f, 0.9510565163f, 0.8090169944f, 0.5877852523f, 0.3090169944f,
                            0.f,-0.3090169944f,-0.5877852523f,-0.8090169944f,-0.9510565163f,
                           -1.f,-0.9510565163f,-0.8090169944f,-0.5877852523f,-0.3090169944f };
    const float C16[16] = { 1.f, 0.9238795325f, 0.7071067812f, 0.3826834324f, 0.f,
                           -0.3826834324f,-0.7071067812f,-0.9238795325f,-1.f,-0.9238795325f,
                           -0.7071067812f,-0.3826834324f, 0.f, 0.3826834324f, 0.7071067812f, 0.9238795325f };
    const float S16[16] = { 0.f, 0.3826834324f, 0.7071067812f, 0.9238795325f, 1.f,
                            0.9238795325f, 0.7071067812f, 0.3826834324f, 0.f,-0.3826834324f,
                           -0.7071067812f,-0.9238795325f,-1.f,-0.9238795325f,-0.7071067812f,-0.3826834324f };

    int blk = blockIdx.x, b = blockIdx.y;
    int tid = threadIdx.x;
    int t0  = blk*NQ;

    __shared__ float2 sH[2][9][20][TF+1];
    __shared__ __align__(16) char pool[SY_BYTES > SFR_BYTES ? SY_BYTES : SFR_BYTES];
    float2* sY  = (float2*)pool;   // [ (beam*TF+f)*162 + k ]
    float*  sFr = (float*)pool;    // [ (beam*TF+f)*322 + n ]  (aliases sY, used after)

    // ======== phase 1: beam (161 threads, serial IIR chain over TF frames) ========
    if(tid < F_){
        int k = tid;
        const float4* gx = (const float4*)g_X + ((size_t)(b*F_ + k))*T_*2;

        const float phi = (float)(6.283185307179586 * 50.0 * 0.027 * 0.6427876096865393 / 340.0);
        float ang = phi * (float)k;
        float s1, c1; sincosf(ang, &s1, &c1);
        float c2 = c1*c1 - s1*s1, s2 = 2.f*c1*s1;
        float c3 = c2*c1 - s2*s1, s3 = s2*c1 + c2*s1;

        float d0=0,d1=0,d2=0,d3=0;
        float2 m10={0,0}, m20={0,0}, m21={0,0}, m30={0,0}, m31={0,0}, m32={0,0};

        int tw = t0 - 1;
        if(tw >= 0){
            #pragma unroll
            for(int j = 0; j < KTAP; j++){
                int s = tw - j;
                if(s < 0) break;
                float cf = (s == 0) ? c_p05[tw] : c_c95[j];
                float4 a = gx[(size_t)s*2], bb = gx[(size_t)s*2+1];
                float2 y0 = make_float2(a.x,a.y), y1 = make_float2(a.z,a.w);
                float2 y2 = make_float2(bb.x,bb.y), y3 = make_float2(bb.z,bb.w);
                d0 += cf*(y0.x*y0.x + y0.y*y0.y);
                d1 += cf*(y1.x*y1.x + y1.y*y1.y);
                d2 += cf*(y2.x*y2.x + y2.y*y2.y);
                d3 += cf*(y3.x*y3.x + y3.y*y3.y);
                m10 = cadd(m10, cscale(cf, cmulc(y1,y0)));
                m20 = cadd(m20, cscale(cf, cmulc(y2,y0)));
                m21 = cadd(m21, cscale(cf, cmulc(y2,y1)));
                m30 = cadd(m30, cscale(cf, cmulc(y3,y0)));
                m31 = cadd(m31, cscale(cf, cmulc(y3,y1)));
                m32 = cadd(m32, cscale(cf, cmulc(y3,y2)));
            }
        }

        #pragma unroll
        for(int i = 0; i < TF; i++){
            int t = t0 + i;
            if(t < T_){
                float4 xa = gx[(size_t)t*2], xb = gx[(size_t)t*2+1];
                float2 X0 = make_float2(xa.x,xa.y), X1 = make_float2(xa.z,xa.w);
                float2 X2 = make_float2(xb.x,xb.y), X3 = make_float2(xb.z,xb.w);

                if(t == 0){
                    d0 = X0.x*X0.x + X0.y*X0.y;
                    d1 = X1.x*X1.x + X1.y*X1.y;
                    d2 = X2.x*X2.x + X2.y*X2.y;
                    d3 = X3.x*X3.x + X3.y*X3.y;
                    m10 = cmulc(X1,X0); m20 = cmulc(X2,X0); m21 = cmulc(X2,X1);
                    m30 = cmulc(X3,X0); m31 = cmulc(X3,X1); m32 = cmulc(X3,X2);
                } else {
                    d0 = 0.05f*d0 + 0.95f*(X0.x*X0.x + X0.y*X0.y);
                    d1 = 0.05f*d1 + 0.95f*(X1.x*X1.x + X1.y*X1.y);
                    d2 = 0.05f*d2 + 0.95f*(X2.x*X2.x + X2.y*X2.y);
                    d3 = 0.05f*d3 + 0.95f*(X3.x*X3.x + X3.y*X3.y);
                    m10 = cadd(cscale(0.05f,m10), cscale(0.95f, cmulc(X1,X0)));
                    m20 = cadd(cscale(0.05f,m20), cscale(0.95f, cmulc(X2,X0)));
                    m21 = cadd(cscale(0.05f,m21), cscale(0.95f, cmulc(X2,X1)));
                    m30 = cadd(cscale(0.05f,m30), cscale(0.95f, cmulc(X3,X0)));
                    m31 = cadd(cscale(0.05f,m31), cscale(0.95f, cmulc(X3,X1)));
                    m32 = cadd(cscale(0.05f,m32), cscale(0.95f, cmulc(X3,X2)));
                }

                float tr4 = 0.25f*(d0+d1+d2+d3);
                float a0 = d0+tr4, a1 = d1+tr4, a2 = d2+tr4, a3 = d3+tr4;

                LDLf f;
                f.iD0 = 1.0f/a0;
                f.L10 = cscale(f.iD0, m10); f.L20 = cscale(f.iD0, m20); f.L30 = cscale(f.iD0, m30);
                float D1 = a1 - (m10.x*f.L10.x + m10.y*f.L10.y);
                f.iD1 = 1.0f/D1;
                float2 t21 = csub(m21, cmulc(m20, f.L10));
                f.L21 = cscale(f.iD1, t21);
                float2 t31 = csub(m31, cmulc(m30, f.L10));
                f.L31 = cscale(f.iD1, t31);
                float D2 = a2 - (m20.x*f.L20.x + m20.y*f.L20.y) - (t21.x*f.L21.x + t21.y*f.L21.y);
                f.iD2 = 1.0f/D2;
                float2 t32 = csub(csub(m32, cmulc(m30, f.L20)), cmulc(t31, f.L21));
                f.L32 = cscale(f.iD2, t32);
                float D3 = a3 - (m30.x*f.L30.x + m30.y*f.L30.y)
                              - (t31.x*f.L31.x + t31.y*f.L31.y)
                              - (t32.x*f.L32.x + t32.y*f.L32.y);
                f.iD3 = 1.0f/D3;

                float2 o1 = mvdr_beam2(f, make_float2(c1,-s1), make_float2(c2,-s2), make_float2(c3,-s3),
                                       X0, X1, X2, X3);
                float2 o2 = mvdr_beam2(f, make_float2(c1, s1), make_float2(c2, s2), make_float2(c3, s3),
                                       X0, X1, X2, X3);
                sY[(0*TF+i)*162 + k] = o1;
                sY[(1*TF+i)*162 + k] = o2;
            } else {
                sY[(0*TF+i)*162 + k] = make_float2(0.f,0.f);
                sY[(1*TF+i)*162 + k] = make_float2(0.f,0.f);
            }
        }
    }
    __syncthreads();

    // ======== phase 2 (stage A): per (beam,k1,f) inverse DFT-20 -> sH ========
    if(tid < 2*9*TF){
        int beam = tid / (9*TF);
        int r    = tid % (9*TF);
        int k1 = r / TF, f = r % TF;
        const float2* yrow = sY + (beam*TF + f)*162;
        float2 z[20];
        #pragma unroll
        for(int k2 = 0; k2 < 20; k2++){
            int kk = 16*k2 + k1;
            float2 v;
            if(kk <= 160){
                v = yrow[kk];
                if(k1 == 0 && (k2 == 0 || k2 == 10)) v.y = 0.f;
            } else {
                v = yrow[320-kk];
                v.y = -v.y;
            }
            z[k2] = v;
        }
        float2 Y[5][4];
        #pragma unroll
        for(int bq = 0; bq < 5; bq++){
            float2 z0=z[bq], z1=z[bq+5], z2=z[bq+10], z3=z[bq+15];
            float2 s0=cadd(z0,z2), s1=csub(z0,z2), s2=cadd(z1,z3), s3=csub(z1,z3);
            Y[bq][0] = cadd(s0,s2);
            Y[bq][2] = csub(s0,s2);
            Y[bq][1] = make_float2(s1.x - s3.y, s1.y + s3.x);
            Y[bq][3] = make_float2(s1.x + s3.y, s1.y - s3.x);
        }
        float sc = (k1==0 || k1==8) ? 1.f : 2.f;
        #pragma unroll
        for(int p = 0; p < 20; p++){
            float2 acc = Y[0][p&3];
            #pragma unroll
            for(int bq = 1; bq < 5; bq++){
                float cw = C20[(bq*p)%20], sw = S20[(bq*p)%20];
                float2 y = Y[bq][p&3];
                acc.x += cw*y.x - sw*y.y;
                acc.y += cw*y.y + sw*y.x;
            }
            sH[beam][k1][p][f] = make_float2(sc*acc.x, sc*acc.y);
        }
    }
    __syncthreads();

    // ======== phase 3 (stage B): twiddle + 9-term DFT-16 -> sFr (aliases sY) ========
    for(int task = tid; task < 2*20*TF; task += 192){
        int beam = task / (20*TF);
        int r    = task % (20*TF);
        int pm = r / TF, f = r % TF;
        float sn, cs; sincospif((float)pm/160.0f, &sn, &cs);
        float2 wst = make_float2(cs, sn), w = make_float2(1.f, 0.f);
        float2 a[9];
        a[0] = sH[beam][0][pm][f];
        #pragma unroll
        for(int k1 = 1; k1 < 9; k1++){
            w = cmul(w, wst);
            a[k1] = cmul(sH[beam][k1][pm][f], w);
        }
        float* frow = sFr + (beam*TF + f)*322;
        #pragma unroll
        for(int u = 0; u < 16; u++){
            float acc = a[0].x;
            #pragma unroll
            for(int k1 = 1; k1 < 9; k1++){
                int j = (k1*u) & 15;
                acc += a[k1].x*C16[j] - a[k1].y*S16[j];
            }
            frow[20*u + pm] = acc * (1.0f/640.0f);
        }
    }
    __syncthreads();

    // ======== phase 4: OLA output ========
    int qmax = min(t0 + NQ, T_ - 1);
    int nq = qmax - t0;
    for(int task = tid; task < 2*nq*80; task += 192){
        int beam = task / (nq*80);
        int r2   = task % (nq*80);
        int qi = r2 / 80;
        int rr = (r2 % 80)*2;
        int q  = t0 + 1 + qi;
        int fq = qi + 1;
        const float* fa = sFr + (beam*TF + fq)*322;
        const float* fb = sFr + (beam*TF + fq - 1)*322;
        float v0 = fa[rr]   + fb[160+rr];
        float v1 = fa[rr+1] + fb[161+rr];
        *(float2*)(out + (size_t)(beam*B_+b)*L_ + (size_t)(q-1)*160 + rr) = make_float2(v0, v1);
    }
}

// ---------------- launch ----------------
extern "C" void kernel_launch(void* const* d_in, const int* in_sizes, int n_in,
                              void* d_out, int out_size){
    const float* x   = (const float*)d_in[0];
    const float* win = (const float*)d_in[1];
    float* out = (float*)d_out;

    k_stats <<<dim3(NCH, B_), 256>>>(x);
    k_stft  <<<dim3((T_+TS4-1)/TS4, B_), 256>>>(x, win);
    k_bistft<<<dim3((T_-1+NQ-1)/NQ, B_), 192>>>(out);
}